// round 14
// baseline (speedup 1.0000x reference)
#include <cuda_runtime.h>
#include <math.h>

constexpr int kT=1024, kH=2048, kNH=16, kNKV=4, kHD=128, kE=8, kI=768;
constexpr int kQKV = kNH*kHD + 2*kNKV*kHD;
constexpr float kEPS=1e-6f, kScale=0.08838834764831845f;
constexpr int kSlots=3072, kTiles=kSlots/128, kStages=3;

__device__ float g_h1[kT*kH];
__device__ float g_qkv[kT*kQKV];
__device__ float g_part[2*kT*kH];
__device__ float g_scores[(size_t)kNH*kT*kT];
__device__ float g_attn[kT*kH];
__device__ float g_h2[(kT+1)*kH];
__device__ float g_h2f[kT*kH];
__device__ float g_gu[(size_t)kSlots*2*kI];
__device__ float g_act[(size_t)kSlots*kI];
__device__ float g_ds[(size_t)kSlots*kH];
__device__ int   g_tok[kSlots];
__device__ float g_wt[kSlots];
__device__ int   g_slot_of[kT*2];
__device__ int   g_topi[kT*2];
__device__ float g_topw[kT*2];
__device__ int   g_cnt[kE];
__device__ int   g_cursor[kE];
__device__ int   g_tile_e[kTiles];
__device__ int   g_ntiles;

__device__ __forceinline__ unsigned f2tf(float x){unsigned r;asm("cvt.rna.tf32.f32 %0, %1;":"=r"(r):"f"(x));return r;}
__device__ __forceinline__ float rtf(float x){return __uint_as_float(f2tf(x));}
__device__ __forceinline__ void mma_tf32(float c[4],unsigned a0,unsigned a1,unsigned a2,unsigned a3,unsigned b0,unsigned b1){
    asm volatile("mma.sync.aligned.m16n8k8.row.col.f32.tf32.tf32.f32 {%0,%1,%2,%3}, {%4,%5,%6,%7}, {%8,%9}, {%0,%1,%2,%3};"
                 :"+f"(c[0]),"+f"(c[1]),"+f"(c[2]),"+f"(c[3]):"r"(a0),"r"(a1),"r"(a2),"r"(a3),"r"(b0),"r"(b1));
}
__device__ __forceinline__ unsigned sptr(const void* p){return (unsigned)__cvta_generic_to_shared(p);}
__device__ __forceinline__ void cp16(unsigned d,const void* s){asm volatile("cp.async.cg.shared.global [%0], [%1], 16;"::"r"(d),"l"(s));}
__device__ __forceinline__ void cp_commit(){asm volatile("cp.async.commit_group;");}
__device__ __forceinline__ void cp_wait1(){asm volatile("cp.async.wait_group 1;");}
__device__ __forceinline__ void ldsm4(unsigned&r0,unsigned&r1,unsigned&r2,unsigned&r3,unsigned a){
    asm volatile("ldmatrix.sync.aligned.m8n8.x4.shared.b16 {%0,%1,%2,%3}, [%4];":"=r"(r0),"=r"(r1),"=r"(r2),"=r"(r3):"r"(a));
}

constexpr int kSA=36, kSB=136, kABuf=128*kSA, kBBuf=32*kSB;
constexpr size_t kPlainSmem=(size_t)kStages*(kABuf+kBBuf)*4;
constexpr size_t kTTSmem=(size_t)kStages*2*kABuf*4;

__device__ __forceinline__ unsigned a_off(int wm,int lane){
    int sub=lane>>3, lr=lane&7;
    return 4u*((wm+(sub&1)*8+lr)*kSA + (sub>>1)*4);
}
__device__ __forceinline__ unsigned b_off(int wn,int p,int lane){
    int sub=lane>>3, lr=lane&7;
    return 4u*((wn+p*16+(sub>>1)*8+lr)*kSA + (sub&1)*4);
}
template <bool DoCvt>
__device__ __forceinline__ void compute_plain(unsigned aB,const unsigned* __restrict__ Bc,int wn,int g,int t,float acc[4][4][4]){
    #pragma unroll
    for (int kk = 0; kk < 32; kk += 8) {
        unsigned a[4][4], b[4][2];
        #pragma unroll
        for (int im = 0; im < 4; im++) ldsm4(a[im][0],a[im][1],a[im][2],a[im][3], aB+4u*(im*16*kSA+kk));
        #pragma unroll
        for (int jn = 0; jn < 4; jn++) {
            unsigned b0 = Bc[(kk+t)*kSB+wn+jn*8+g];
            unsigned b1 = Bc[(kk+t+4)*kSB+wn+jn*8+g];
            if (DoCvt) { b[jn][0]=f2tf(__uint_as_float(b0)); b[jn][1]=f2tf(__uint_as_float(b1)); }
            else       { b[jn][0]=b0; b[jn][1]=b1; }
        }
        #pragma unroll
        for (int im = 0; im < 4; im++)
            #pragma unroll
            for (int jn = 0; jn < 4; jn++)
                mma_tf32(acc[im][jn],a[im][0],a[im][1],a[im][2],a[im][3],b[jn][0],b[jn][1]);
    }
}
__device__ __forceinline__ void compute_tt(unsigned aB,unsigned b0a,unsigned b1a,float acc[4][4][4]){
    #pragma unroll
    for (int kk = 0; kk < 32; kk += 8) {
        unsigned a[4][4], b[4][2];
        #pragma unroll
        for (int im = 0; im < 4; im++) ldsm4(a[im][0],a[im][1],a[im][2],a[im][3], aB+4u*(im*16*kSA+kk));
        ldsm4(b[0][0],b[0][1],b[1][0],b[1][1], b0a+4u*kk);
        ldsm4(b[2][0],b[2][1],b[3][0],b[3][1], b1a+4u*kk);
        #pragma unroll
        for (int im = 0; im < 4; im++)
            #pragma unroll
            for (int jn = 0; jn < 4; jn++)
                mma_tf32(acc[im][jn],a[im][0],a[im][1],a[im][2],a[im][3],b[jn][0],b[jn][1]);
    }
}

// ---------------- fused add + RMSNorm (float4) ----------------
__global__ void add_rms_kernel(const float* __restrict__ x,const float* __restrict__ r,
                               const float* __restrict__ w,float* __restrict__ res_out,
                               float* __restrict__ h_out,float* __restrict__ h_full){
    const int t = blockIdx.x, tid = threadIdx.x;
    const float4* xp = (const float4*)(x + (size_t)t*kH);
    const float4* rp = r ? (const float4*)(r + (size_t)t*kH) : nullptr;
    float4 v[2]; float ss = 0.f;
    #pragma unroll
    for (int i = 0; i < 2; i++) {
        int idx = tid + i*256;
        float4 a = xp[idx];
        if (rp) { float4 b = rp[idx]; a.x+=b.x; a.y+=b.y; a.z+=b.z; a.w+=b.w; }
        v[i] = a; ss += a.x*a.x + a.y*a.y + a.z*a.z + a.w*a.w;
    }
    __shared__ float sh[256];
    sh[tid] = ss; __syncthreads();
    for (int s = 128; s > 0; s >>= 1) { if (tid < s) sh[tid] += sh[tid+s]; __syncthreads(); }
    float scale = rsqrtf(sh[0]/(float)kH + kEPS);
    #pragma unroll
    for (int i = 0; i < 2; i++) {
        int idx = tid + i*256;
        if (res_out) ((float4*)(res_out + (size_t)t*kH))[idx] = v[i];
        float4 wv = ((const float4*)w)[idx];
        float4 hv = make_float4(v[i].x*scale*wv.x, v[i].y*scale*wv.y,
                                v[i].z*scale*wv.z, v[i].w*scale*wv.w);
        ((float4*)(h_out + (size_t)t*kH))[idx] =
            make_float4(rtf(hv.x), rtf(hv.y), rtf(hv.z), rtf(hv.w));
        if (h_full) ((float4*)(h_full + (size_t)t*kH))[idx] = hv;
    }
}

// fused: h = p0 + p1 + res_in (o-proj reduce absorbed), float4
__global__ void add_rms3_kernel(const float* __restrict__ p0,const float* __restrict__ p1,
                                const float* __restrict__ w,float* __restrict__ res_io,
                                float* __restrict__ h_out,float* __restrict__ h_full){
    const int t = blockIdx.x, tid = threadIdx.x;
    float4 v[2]; float ss = 0.f;
    #pragma unroll
    for (int i = 0; i < 2; i++) {
        int idx = tid + i*256;
        size_t o = (size_t)t*(kH/4) + idx;
        float4 a = ((const float4*)p0)[o];
        float4 b = ((const float4*)p1)[o];
        float4 c = ((const float4*)res_io)[o];
        float4 s4 = make_float4(a.x+b.x+c.x, a.y+b.y+c.y, a.z+b.z+c.z, a.w+b.w+c.w);
        v[i] = s4; ss += s4.x*s4.x + s4.y*s4.y + s4.z*s4.z + s4.w*s4.w;
    }
    __shared__ float sh[256];
    sh[tid] = ss; __syncthreads();
    for (int s = 128; s > 0; s >>= 1) { if (tid < s) sh[tid] += sh[tid+s]; __syncthreads(); }
    float scale = rsqrtf(sh[0]/(float)kH + kEPS);
    #pragma unroll
    for (int i = 0; i < 2; i++) {
        int idx = tid + i*256;
        size_t o = (size_t)t*(kH/4) + idx;
        ((float4*)res_io)[o] = v[i];
        float4 wv = ((const float4*)w)[idx];
        float4 hv = make_float4(v[i].x*scale*wv.x, v[i].y*scale*wv.y,
                                v[i].z*scale*wv.z, v[i].w*scale*wv.w);
        ((float4*)h_out)[o] = make_float4(rtf(hv.x), rtf(hv.y), rtf(hv.z), rtf(hv.w));
        if (h_full) ((float4*)h_full)[o] = hv;
    }
}

// ---------------- 128x128 GEMM; split factor = gridDim.z ----------------
__global__ void __launch_bounds__(256, 2)
gemm_splitk_kernel(const float* __restrict__ A,int lda,const float* __restrict__ B,int ldb,
                   float* __restrict__ Cpart,int ldc,int Kdim){
    extern __shared__ unsigned smem[];
    unsigned* As = smem;
    unsigned* Bs = smem + kStages*kABuf;
    const int row0 = blockIdx.x*128, col0 = blockIdx.y*128;
    const int Kpart = Kdim / gridDim.z;
    const int koff = blockIdx.z*Kpart;
    const int tid = threadIdx.x, lane = tid&31, warp = tid>>5;
    const int wm = (warp&1)*64, wn = (warp>>1)*32;
    const int g = lane>>2, t = lane&3;
    const float* Ab = A + (size_t)row0*lda + koff;
    const float* Bb = B + (size_t)koff*ldb + col0;
    float* C = Cpart + (size_t)blockIdx.z*kT*ldc;
    const int nk = Kpart >> 5;

    auto issue = [&](int s){
        unsigned* Ad = As + (s%kStages)*kABuf;
        unsigned* Bd = Bs + (s%kStages)*kBBuf;
        int kk0 = s*32;
        #pragma unroll
        for (int q = 0; q < 4; q++) {
            int e = tid + q*256;
            int m = e>>3, k4 = e&7;
            cp16(sptr(Ad + m*kSA + k4*4), Ab + (size_t)m*lda + kk0 + k4*4);
        }
        #pragma unroll
        for (int q = 0; q < 4; q++) {
            int e = tid + q*256;
            int k = e>>5, n16 = e&31;
            cp16(sptr(Bd + k*kSB + n16*4), Bb + (size_t)(kk0+k)*ldb + n16*4);
        }
        cp_commit();
    };
    for (int s = 0; s < kStages-1; s++) { if (s < nk) issue(s); else cp_commit(); }

    const unsigned aO = a_off(wm,lane);
    float acc[4][4][4] = {};
    for (int i = 0; i < nk; i++) {
        cp_wait1();
        __syncthreads();
        int s = i + kStages - 1;
        if (s < nk) issue(s); else cp_commit();
        compute_plain<true>(sptr(As + (i%kStages)*kABuf) + aO, Bs + (i%kStages)*kBBuf, wn, g, t, acc);
    }
    #pragma unroll
    for (int im = 0; im < 4; im++)
        #pragma unroll
        for (int jn = 0; jn < 4; jn++) {
            int r0 = row0 + wm + im*16 + g;
            int c0 = col0 + wn + jn*8 + 2*t;
            #pragma unroll
            for (int hh = 0; hh < 2; hh++) {
                int rr = r0 + hh*8;
                C[(size_t)rr*ldc + c0]   = acc[im][jn][hh*2+0];
                C[(size_t)rr*ldc + c0+1] = acc[im][jn][hh*2+1];
            }
        }
}

// ---------------- QK-RMSNorm + RoPE (in place); V rounded ----------------
__global__ void rope_kernel(const int* __restrict__ positions,const float* __restrict__ q_norm_w,
                            const float* __restrict__ k_norm_w){
    const int t = blockIdx.x, hh = blockIdx.y, lane = threadIdx.x;
    if (hh >= kNH + kNKV) {
        int vh = hh - kNH - kNKV;
        float* ptr = g_qkv + (size_t)t*kQKV + (kNH+kNKV)*kHD + vh*kHD;
        ptr[lane] = rtf(ptr[lane]);
        return;
    }
    float* ptr = g_qkv + (size_t)t*kQKV + (hh < kNH ? hh*kHD : kNH*kHD + (hh-kNH)*kHD);
    const float* nw = (hh < kNH) ? q_norm_w : k_norm_w;
    float v = ptr[lane];
    __shared__ float sred[128];
    sred[lane] = v*v; __syncthreads();
    for (int s = 64; s > 0; s >>= 1) { if (lane < s) sred[lane] += sred[lane+s]; __syncthreads(); }
    float scale = rsqrtf(sred[0]/(float)kHD + kEPS);
    float xn = v*scale*nw[lane];
    __shared__ float sh[128];
    sh[lane] = xn; __syncthreads();
    int j = lane & 63;
    const float kLog2Theta_64 = 19.931568569324174f / 64.0f;
    float inv = exp2f(-(float)j * kLog2Theta_64);
    float ang = (float)positions[t] * inv;
    float s, c;
    sincosf(ang, &s, &c);
    float outv = (lane < 64) ? sh[lane]*c - sh[lane+64]*s : sh[lane]*c + sh[lane-64]*s;
    ptr[lane] = rtf(outv);
}

__global__ void __launch_bounds__(256,2) scores_kernel(){
    const int qt = blockIdx.x, kt = blockIdx.y, h = blockIdx.z;
    if (kt > qt) return;
    extern __shared__ unsigned smw[];
    unsigned* As = smw;
    unsigned* Bst = smw + kStages*kABuf;
    const float* Q  = g_qkv + (size_t)qt*128*kQKV + h*kHD;
    const float* Kp = g_qkv + (size_t)kt*128*kQKV + kNH*kHD + (h>>2)*kHD;
    const int tid = threadIdx.x, lane = tid&31, warp = tid>>5;
    const int wm = (warp&1)*64, wn = (warp>>1)*32;
    const int g = lane>>2, t = lane&3;
    const int nk = kHD >> 5;
    auto issue = [&](int s){
        unsigned* Ad = As + (s%kStages)*kABuf;
        unsigned* Bd = Bst + (s%kStages)*kABuf;
        int kk0 = s*32;
        #pragma unroll
        for (int q = 0; q < 4; q++) {
            int e = tid + q*256;
            int m = e>>3, k4 = e&7;
            cp16(sptr(Ad + m*kSA + k4*4), Q  + (size_t)m*kQKV + kk0 + k4*4);
            cp16(sptr(Bd + m*kSA + k4*4), Kp + (size_t)m*kQKV + kk0 + k4*4);
        }
        cp_commit();
    };
    for (int s = 0; s < kStages-1; s++) { if (s < nk) issue(s); else cp_commit(); }
    const unsigned aO = a_off(wm,lane), b0 = b_off(wn,0,lane), b1 = b_off(wn,1,lane);
    float acc[4][4][4] = {};
    for (int i = 0; i < nk; i++) {
        cp_wait1();
        __syncthreads();
        int s = i + kStages - 1;
        if (s < nk) issue(s); else cp_commit();
        int p = i % kStages;
        compute_tt(sptr(As+p*kABuf)+aO, sptr(Bst+p*kABuf)+b0, sptr(Bst+p*kABuf)+b1, acc);
    }
    const int row0 = qt*128, col0 = kt*128;
    #pragma unroll
    for (int im = 0; im < 4; im++)
        #pragma unroll
        for (int jn = 0; jn < 4; jn++) {
            int r0 = row0 + wm + im*16 + g;
            int c0 = col0 + wn + jn*8 + 2*t;
            #pragma unroll
            for (int hh = 0; hh < 2; hh++) {
                int qi = r0 + hh*8;
                float v0 = acc[im][jn][hh*2+0]*kScale;
                float v1 = acc[im][jn][hh*2+1]*kScale;
                if (c0   > qi) v0 = -1e9f;
                if (c0+1 > qi) v1 = -1e9f;
                g_scores[((size_t)h*kT+qi)*kT + c0]   = v0;
                g_scores[((size_t)h*kT+qi)*kT + c0+1] = v1;
            }
        }
}

// ---------------- row softmax, float4 (masked entries -1e9 -> exp 0 automatically) ----------------
__global__ void softmax_kernel(){
    const int q = blockIdx.x, h = blockIdx.y, tid = threadIdx.x;
    float4* row4 = (float4*)(g_scores + ((size_t)h*kT + q)*kT);
    const int n4 = ((q>>7)+1) << 5;   // tend/4
    __shared__ float sh[256];
    float lmax = -3.4e38f;
    for (int i = tid; i < n4; i += 256) {
        float4 v = row4[i];
        lmax = fmaxf(lmax, fmaxf(fmaxf(v.x, v.y), fmaxf(v.z, v.w)));
    }
    sh[tid] = lmax; __syncthreads();
    for (int s = 128; s > 0; s >>= 1) { if (tid < s) sh[tid] = fmaxf(sh[tid], sh[tid+s]); __syncthreads(); }
    float m = sh[0]; __syncthreads();
    float lsum = 0.f;
    for (int i = tid; i < n4; i += 256) {
        float4 v = row4[i];
        v.x = __expf(v.x - m); v.y = __expf(v.y - m);
        v.z = __expf(v.z - m); v.w = __expf(v.w - m);
        row4[i] = v;
        lsum += v.x + v.y + v.z + v.w;
    }
    sh[tid] = lsum; __syncthreads();
    for (int s = 128; s > 0; s >>= 1) { if (tid < s) sh[tid] += sh[tid+s]; __syncthreads(); }
    float inv = 1.f/sh[0];
    for (int i = tid; i < n4; i += 256) {
        float4 v = row4[i];
        row4[i] = make_float4(rtf(v.x*inv), rtf(v.y*inv), rtf(v.z*inv), rtf(v.w*inv));
    }
}

__global__ void __launch_bounds__(256,2) pv_kernel(){
    const int qt = blockIdx.x, h = blockIdx.y;
    extern __shared__ unsigned smw[];
    unsigned* As = smw;
    unsigned* Bs = smw + kStages*kABuf;
    const int row0 = qt*128;
    const int Kdim = (qt+1)*128;
    const float* A = g_scores + ((size_t)h*kT + row0)*kT;
    const float* B = g_qkv + (kNH+kNKV)*kHD + (h>>2)*kHD;
    const int tid = threadIdx.x, lane = tid&31, warp = tid>>5;
    const int wm = (warp&1)*64, wn = (warp>>1)*32;
    const int g = lane>>2, t = lane&3;
    const int nk = Kdim >> 5;
    auto issue = [&](int s){
        unsigned* Ad = As + (s%kStages)*kABuf;
        unsigned* Bd = Bs + (s%kStages)*kBBuf;
        int kk0 = s*32;
        #pragma unroll
        for (int q = 0; q < 4; q++) {
            int e = tid + q*256;
            int m = e>>3, k4 = e&7;
            cp16(sptr(Ad + m*kSA + k4*4), A + (size_t)m*kT + kk0 + k4*4);
        }
        #pragma unroll
        for (int q = 0; q < 4; q++) {
            int e = tid + q*256;
            int k = e>>5, n16 = e&31;
            cp16(sptr(Bd + k*kSB + n16*4), B + (size_t)(kk0+k)*kQKV + n16*4);
        }
        cp_commit();
    };
    for (int s = 0; s < kStages-1; s++) { if (s < nk) issue(s); else cp_commit(); }
    const unsigned aO = a_off(wm,lane);
    float acc[4][4][4] = {};
    for (int i = 0; i < nk; i++) {
        cp_wait1();
        __syncthreads();
        int s = i + kStages - 1;
        if (s < nk) issue(s); else cp_commit();
        int p = i % kStages;
        compute_plain<false>(sptr(As+p*kABuf)+aO, Bs+p*kBBuf, wn, g, t, acc);
    }
    #pragma unroll
    for (int im = 0; im < 4; im++)
        #pragma unroll
        for (int jn = 0; jn < 4; jn++) {
            int r0 = row0 + wm + im*16 + g;
            int c0 = wn + jn*8 + 2*t;
            #pragma unroll
            for (int hh = 0; hh < 2; hh++) {
                int rr = r0 + hh*8;
                g_attn[(size_t)rr*kH + h*kHD + c0]   = rtf(acc[im][jn][hh*2+0]);
                g_attn[(size_t)rr*kH + h*kHD + c0+1] = rtf(acc[im][jn][hh*2+1]);
            }
        }
}

__global__ void router_kernel(const float* __restrict__ gate_w){
    const int t = blockIdx.x, tid = threadIdx.x;
    const float* hp = g_h2f + (size_t)t*kH;
    float acc[kE] = {};
    for (int k = tid; k < kH; k += 256) {
        float hv = hp[k];
        const float* gw = gate_w + (size_t)k*kE;
        #pragma unroll
        for (int e = 0; e < kE; e++) acc[e] += hv*gw[e];
    }
    __shared__ float sh[kE][256];
    #pragma unroll
    for (int e = 0; e < kE; e++) sh[e][tid] = acc[e];
    __syncthreads();
    for (int s = 128; s > 0; s >>= 1) {
        if (tid < s) {
            #pragma unroll
            for (int e = 0; e < kE; e++) sh[e][tid] += sh[e][tid+s];
        }
        __syncthreads();
    }
    if (tid == 0) {
        float l[kE], mx = -3.4e38f;
        #pragma unroll
        for (int e = 0; e < kE; e++) { l[e] = sh[e][0]; mx = fmaxf(mx, l[e]); }
        float sum = 0.f;
        #pragma unroll
        for (int e = 0; e < kE; e++) { l[e] = __expf(l[e]-mx); sum += l[e]; }
        float isum = 1.f/sum;
        float best = -1.f, second = -1.f; int bi = 0, si = 0;
        #pragma unroll
        for (int e = 0; e < kE; e++) {
            float p = l[e]*isum;
            if (p > best) { second = best; si = bi; best = p; bi = e; }
            else if (p > second) { second = p; si = e; }
        }
        float denom = 1.f/(best + second);
        g_topi[t*2]   = bi; g_topw[t*2]   = best*denom;
        g_topi[t*2+1] = si; g_topw[t*2+1] = second*denom;
        atomicAdd(&g_cnt[bi], 1);
        atomicAdd(&g_cnt[si], 1);
    }
}

__global__ void moe_init_kernel(){
    int i = blockIdx.x*256 + threadIdx.x;
    if (i < kE) g_cnt[i] = 0;
    if (i < kSlots) g_tok[i] = kT;
    if (i < kH) g_h2[(size_t)kT*kH + i] = 0.f;
}
__global__ void moe_setup_kernel(){
    int off = 0, tile = 0;
    for (int e = 0; e < kE; e++) {
        g_cursor[e] = off;
        int seg = ((g_cnt[e] + 127)/128)*128;
        for (int i = 0; i < seg/128; i++) g_tile_e[tile++] = e;
        off += seg;
    }
    g_ntiles = tile;
}
__global__ void moe_scatter_kernel(){
    int t = blockIdx.x*256 + threadIdx.x;
    if (t >= kT) return;
    #pragma unroll
    for (int k = 0; k < 2; k++) {
        int e = g_topi[t*2+k];
        int pos = atomicAdd(&g_cursor[e], 1);
        g_tok[pos] = t;
        g_wt[pos]  = g_topw[t*2+k];
        g_slot_of[t*2+k] = pos;
    }
}

__global__ void __launch_bounds__(256,2) moe_gu_kernel(const float* __restrict__ w_gate_up){
    const int tile = blockIdx.x;
    if (tile >= g_ntiles) return;
    extern __shared__ unsigned smw[];
    unsigned* As = smw;
    unsigned* Bs = smw + kStages*kABuf;
    __shared__ int rows[128];
    const int tid = threadIdx.x;
    if (tid < 128) rows[tid] = g_tok[tile*128 + tid];
    __syncthreads();
    const int e = g_tile_e[tile];
    const int col0 = blockIdx.y*128;
    const float* Bb = w_gate_up + (size_t)e*kH*2*kI + col0;
    const int lane = tid&31, warp = tid>>5;
    const int wm = (warp&1)*64, wn = (warp>>1)*32;
    const int g = lane>>2, t = lane&3;
    const int nk = kH >> 5;
    auto issue = [&](int s){
        unsigned* Ad = As + (s%kStages)*kABuf;
        unsigned* Bd = Bs + (s%kStages)*kBBuf;
        int kk0 = s*32;
        #pragma unroll
        for (int q = 0; q < 4; q++) {
            int ee = tid + q*256;
            int m = ee>>3, k4 = ee&7;
            cp16(sptr(Ad + m*kSA + k4*4), g_h2 + (size_t)rows[m]*kH + kk0 + k4*4);
        }
        #pragma unroll
        for (int q = 0; q < 4; q++) {
            int ee = tid + q*256;
            int k = ee>>5, n16 = ee&31;
            cp16(sptr(Bd + k*kSB + n16*4), Bb + (size_t)(kk0+k)*(2*kI) + n16*4);
        }
        cp_commit();
    };
    for (int s = 0; s < kStages-1; s++) { if (s < nk) issue(s); else cp_commit(); }
    const unsigned aO = a_off(wm,lane);
    float acc[4][4][4] = {};
    for (int i = 0; i < nk; i++) {
        cp_wait1();
        __syncthreads();
        int s = i + kStages - 1;
        if (s < nk) issue(s); else cp_commit();
        int p = i % kStages;
        compute_plain<true>(sptr(As+p*kABuf)+aO, Bs+p*kBBuf, wn, g, t, acc);
    }
    #pragma unroll
    for (int im = 0; im < 4; im++)
        #pragma unroll
        for (int jn = 0; jn < 4; jn++) {
            int r0 = wm + im*16 + g;
            int c0 = col0 + wn + jn*8 + 2*t;
            #pragma unroll
            for (int hh = 0; hh < 2; hh++) {
                int slot = tile*128 + r0 + hh*8;
                g_gu[(size_t)slot*2*kI + c0]   = acc[im][jn][hh*2+0];
                g_gu[(size_t)slot*2*kI + c0+1] = acc[im][jn][hh*2+1];
            }
        }
}

__global__ void silu_kernel(){
    int idx = blockIdx.x*256 + threadIdx.x;          // over slots * kI/4
    int slot = idx / (kI/4), j4 = idx % (kI/4);
    if (slot >= g_ntiles*128) return;
    float4 gv = ((const float4*)(g_gu + (size_t)slot*2*kI))[j4];
    float4 uv = ((const float4*)(g_gu + (size_t)slot*2*kI + kI))[j4];
    float4 o;
    o.x = rtf((gv.x / (1.f + __expf(-gv.x))) * uv.x);
    o.y = rtf((gv.y / (1.f + __expf(-gv.y))) * uv.y);
    o.z = rtf((gv.z / (1.f + __expf(-gv.z))) * uv.z);
    o.w = rtf((gv.w / (1.f + __expf(-gv.w))) * uv.w);
    ((float4*)(g_act))[(size_t)slot*(kI/4) + j4] = o;
}

__global__ void __launch_bounds__(256,2) moe_down_kernel(const float* __restrict__ w_down){
    const int tile = blockIdx.x;
    if (tile >= g_ntiles) return;
    extern __shared__ unsigned smw[];
    unsigned* As = smw;
    unsigned* Bs = smw + kStages*kABuf;
    const int e = g_tile_e[tile];
    const int col0 = blockIdx.y*128;
    const float* A  = g_act + (size_t)tile*128*kI;
    const float* Bb = w_down + (size_t)e*kI*kH + col0;
    const int tid = threadIdx.x, lane = tid&31, warp = tid>>5;
    const int wm = (warp&1)*64, wn = (warp>>1)*32;
    const int g = lane>>2, t = lane&3;
    const int nk = kI >> 5;
    auto issue = [&](int s){
        unsigned* Ad = As + (s%kStages)*kABuf;
        unsigned* Bd = Bs + (s%kStages)*kBBuf;
        int kk0 = s*32;
        #pragma unroll
        for (int q = 0; q < 4; q++) {
            int ee = tid + q*256;
            int m = ee>>3, k4 = ee&7;
            cp16(sptr(Ad + m*kSA + k4*4), A + (size_t)m*kI + kk0 + k4*4);
        }
        #pragma unroll
        for (int q = 0; q < 4; q++) {
            int ee = tid + q*256;
            int k = ee>>5, n16 = ee&31;
            cp16(sptr(Bd + k*kSB + n16*4), Bb + (size_t)(kk0+k)*kH + n16*4);
        }
        cp_commit();
    };
    for (int s = 0; s < kStages-1; s++) { if (s < nk) issue(s); else cp_commit(); }
    const unsigned aO = a_off(wm,lane);
    float acc[4][4][4] = {};
    for (int i = 0; i < nk; i++) {
        cp_wait1();
        __syncthreads();
        int s = i + kStages - 1;
        if (s < nk) issue(s); else cp_commit();
        int p = i % kStages;
        compute_plain<true>(sptr(As+p*kABuf)+aO, Bs+p*kBBuf, wn, g, t, acc);
    }
    #pragma unroll
    for (int im = 0; im < 4; im++)
        #pragma unroll
        for (int jn = 0; jn < 4; jn++) {
            int r0 = wm + im*16 + g;
            int c0 = col0 + wn + jn*8 + 2*t;
            #pragma unroll
            for (int hh = 0; hh < 2; hh++) {
                int slot = tile*128 + r0 + hh*8;
                g_ds[(size_t)slot*kH + c0]   = acc[im][jn][hh*2+0];
                g_ds[(size_t)slot*kH + c0+1] = acc[im][jn][hh*2+1];
            }
        }
}

__global__ void combine_kernel(float* __restrict__ out){
    const int t = blockIdx.x;
    const int s0 = g_slot_of[t*2], s1 = g_slot_of[t*2+1];
    const float w0 = g_wt[s0], w1 = g_wt[s1];
    const float4* d0 = (const float4*)(g_ds + (size_t)s0*kH);
    const float4* d1 = (const float4*)(g_ds + (size_t)s1*kH);
    float4* o = (float4*)(out + (size_t)t*kH);
    for (int j = threadIdx.x; j < kH/4; j += 256) {
        float4 a = d0[j], b = d1[j];
        o[j] = make_float4(w0*a.x + w1*b.x, w0*a.y + w1*b.y,
                           w0*a.z + w1*b.z, w0*a.w + w1*b.w);
    }
}

extern "C" void kernel_launch(void* const* d_in, const int* in_sizes, int n_in,
                              void* d_out, int out_size) {
    const int*   positions = (const int*)  d_in[0];
    const float* hidden    = (const float*)d_in[1];
    const float* residual  = (const float*)d_in[2];
    const float* w_qkv     = (const float*)d_in[3];
    const float* w_o       = (const float*)d_in[4];
    const float* q_norm_w  = (const float*)d_in[5];
    const float* k_norm_w  = (const float*)d_in[6];
    const float* ln1_w     = (const float*)d_in[7];
    const float* ln2_w     = (const float*)d_in[8];
    const float* gate_w    = (const float*)d_in[9];
    const float* w_gate_up = (const float*)d_in[10];
    const float* w_down    = (const float*)d_in[11];
    float* out = (float*)d_out;
    float* res = out + (size_t)kT*kH;

    float* d_h1;   cudaGetSymbolAddress((void**)&d_h1,  g_h1);
    float* d_qkv;  cudaGetSymbolAddress((void**)&d_qkv, g_qkv);
    float* d_part; cudaGetSymbolAddress((void**)&d_part,g_part);
    float* d_attn; cudaGetSymbolAddress((void**)&d_attn,g_attn);
    float* d_h2;   cudaGetSymbolAddress((void**)&d_h2,  g_h2);
    float* d_h2f;  cudaGetSymbolAddress((void**)&d_h2f, g_h2f);

    cudaFuncSetAttribute(gemm_splitk_kernel, cudaFuncAttributeMaxDynamicSharedMemorySize, (int)kPlainSmem);
    cudaFuncSetAttribute(scores_kernel,      cudaFuncAttributeMaxDynamicSharedMemorySize, (int)kTTSmem);
    cudaFuncSetAttribute(pv_kernel,          cudaFuncAttributeMaxDynamicSharedMemorySize, (int)kPlainSmem);
    cudaFuncSetAttribute(moe_gu_kernel,      cudaFuncAttributeMaxDynamicSharedMemorySize, (int)kPlainSmem);
    cudaFuncSetAttribute(moe_down_kernel,    cudaFuncAttributeMaxDynamicSharedMemorySize, (int)kPlainSmem);

    add_rms_kernel<<<kT, 256>>>(hidden, residual, ln1_w, res, d_h1, nullptr);
    // QKV: unsplit (z=1), writes g_qkv directly
    gemm_splitk_kernel<<<dim3(kT/128, kQKV/128, 1), 256, kPlainSmem>>>(d_h1, kH, w_qkv, kQKV, d_qkv, kQKV, kH);
    rope_kernel<<<dim3(kT, kNH + 2*kNKV), 128>>>(positions, q_norm_w, k_norm_w);
    scores_kernel<<<dim3(kT/128, kT/128, kNH), 256, kTTSmem>>>();
    softmax_kernel<<<dim3(kT, kNH), 256>>>();
    pv_kernel<<<dim3(kT/128, kNH), 256, kPlainSmem>>>();
    // O-proj: split-K2 into partials; reduce fused into add_rms3
    gemm_splitk_kernel<<<dim3(kT/128, kH/128, 2), 256, kPlainSmem>>>(d_attn, kH, w_o, kH, d_part, kH, kH);
    add_rms3_kernel<<<kT, 256>>>(d_part, d_part + (size_t)kT*kH, ln2_w, res, d_h2, d_h2f);
    moe_init_kernel<<<(kSlots + 255)/256, 256>>>();
    router_kernel<<<kT, 256>>>(gate_w);
    moe_setup_kernel<<<1, 1>>>();
    moe_scatter_kernel<<<(kT + 255)/256, 256>>>();
    moe_gu_kernel<<<dim3(kTiles, 2*kI/128), 256, kPlainSmem>>>(w_gate_up);
    silu_kernel<<<(kSlots*(kI/4) + 255)/256, 256>>>();
    moe_down_kernel<<<dim3(kTiles, kH/128), 256, kPlainSmem>>>(w_down);
    combine_kernel<<<kT, 256>>>(out);
}

// round 15
// speedup vs baseline: 1.0470x; 1.0470x over previous
#include <cuda_runtime.h>
#include <math.h>

constexpr int kT=1024, kH=2048, kNH=16, kNKV=4, kHD=128, kE=8, kI=768;
constexpr int kQKV = kNH*kHD + 2*kNKV*kHD;
constexpr float kEPS=1e-6f, kScale=0.08838834764831845f;
constexpr int kSlots=3072, kTiles=kSlots/128, kStages=3;

__device__ float g_h1[kT*kH];
__device__ float g_qkv[kT*kQKV];
__device__ float g_part[2*kT*kQKV];
__device__ float g_scores[(size_t)kNH*kT*kT];
__device__ float g_attn[kT*kH];
__device__ float g_h2[(kT+1)*kH];
__device__ float g_h2f[kT*kH];
__device__ float g_gu[(size_t)kSlots*2*kI];
__device__ float g_act[(size_t)kSlots*kI];
__device__ float g_ds[(size_t)kSlots*kH];
__device__ int   g_tok[kSlots];
__device__ float g_wt[kSlots];
__device__ int   g_slot_of[kT*2];
__device__ int   g_topi[kT*2];
__device__ float g_topw[kT*2];
__device__ int   g_cnt[kE];
__device__ int   g_cursor[kE];
__device__ int   g_tile_e[kTiles];
__device__ int   g_ntiles;

__device__ __forceinline__ unsigned f2tf(float x){unsigned r;asm("cvt.rna.tf32.f32 %0, %1;":"=r"(r):"f"(x));return r;}
__device__ __forceinline__ float rtf(float x){return __uint_as_float(f2tf(x));}
__device__ __forceinline__ void mma_tf32(float c[4],unsigned a0,unsigned a1,unsigned a2,unsigned a3,unsigned b0,unsigned b1){
    asm volatile("mma.sync.aligned.m16n8k8.row.col.f32.tf32.tf32.f32 {%0,%1,%2,%3}, {%4,%5,%6,%7}, {%8,%9}, {%0,%1,%2,%3};"
                 :"+f"(c[0]),"+f"(c[1]),"+f"(c[2]),"+f"(c[3]):"r"(a0),"r"(a1),"r"(a2),"r"(a3),"r"(b0),"r"(b1));
}
__device__ __forceinline__ unsigned sptr(const void* p){return (unsigned)__cvta_generic_to_shared(p);}
__device__ __forceinline__ void cp16(unsigned d,const void* s){asm volatile("cp.async.cg.shared.global [%0], [%1], 16;"::"r"(d),"l"(s));}
__device__ __forceinline__ void cp_commit(){asm volatile("cp.async.commit_group;");}
__device__ __forceinline__ void cp_wait1(){asm volatile("cp.async.wait_group 1;");}
__device__ __forceinline__ void ldsm4(unsigned&r0,unsigned&r1,unsigned&r2,unsigned&r3,unsigned a){
    asm volatile("ldmatrix.sync.aligned.m8n8.x4.shared.b16 {%0,%1,%2,%3}, [%4];":"=r"(r0),"=r"(r1),"=r"(r2),"=r"(r3):"r"(a));
}

constexpr int kSA=36, kSB=136, kABuf=128*kSA, kBBuf=32*kSB;
constexpr size_t kPlainSmem=(size_t)kStages*(kABuf+kBBuf)*4;
constexpr size_t kTTSmem=(size_t)kStages*2*kABuf*4;

__device__ __forceinline__ unsigned a_off(int wm,int lane){
    int sub=lane>>3, lr=lane&7;
    return 4u*((wm+(sub&1)*8+lr)*kSA + (sub>>1)*4);
}
__device__ __forceinline__ unsigned b_off(int wn,int p,int lane){
    int sub=lane>>3, lr=lane&7;
    return 4u*((wn+p*16+(sub>>1)*8+lr)*kSA + (sub&1)*4);
}
template <bool DoCvt>
__device__ __forceinline__ void compute_plain(unsigned aB,const unsigned* __restrict__ Bc,int wn,int g,int t,float acc[4][4][4]){
    #pragma unroll
    for (int kk = 0; kk < 32; kk += 8) {
        unsigned a[4][4], b[4][2];
        #pragma unroll
        for (int im = 0; im < 4; im++) ldsm4(a[im][0],a[im][1],a[im][2],a[im][3], aB+4u*(im*16*kSA+kk));
        #pragma unroll
        for (int jn = 0; jn < 4; jn++) {
            unsigned b0 = Bc[(kk+t)*kSB+wn+jn*8+g];
            unsigned b1 = Bc[(kk+t+4)*kSB+wn+jn*8+g];
            if (DoCvt) { b[jn][0]=f2tf(__uint_as_float(b0)); b[jn][1]=f2tf(__uint_as_float(b1)); }
            else       { b[jn][0]=b0; b[jn][1]=b1; }
        }
        #pragma unroll
        for (int im = 0; im < 4; im++)
            #pragma unroll
            for (int jn = 0; jn < 4; jn++)
                mma_tf32(acc[im][jn],a[im][0],a[im][1],a[im][2],a[im][3],b[jn][0],b[jn][1]);
    }
}
__device__ __forceinline__ void compute_tt(unsigned aB,unsigned b0a,unsigned b1a,float acc[4][4][4]){
    #pragma unroll
    for (int kk = 0; kk < 32; kk += 8) {
        unsigned a[4][4], b[4][2];
        #pragma unroll
        for (int im = 0; im < 4; im++) ldsm4(a[im][0],a[im][1],a[im][2],a[im][3], aB+4u*(im*16*kSA+kk));
        ldsm4(b[0][0],b[0][1],b[1][0],b[1][1], b0a+4u*kk);
        ldsm4(b[2][0],b[2][1],b[3][0],b[3][1], b1a+4u*kk);
        #pragma unroll
        for (int im = 0; im < 4; im++)
            #pragma unroll
            for (int jn = 0; jn < 4; jn++)
                mma_tf32(acc[im][jn],a[im][0],a[im][1],a[im][2],a[im][3],b[jn][0],b[jn][1]);
    }
}

// ---------------- fused add + RMSNorm (float4) ----------------
__global__ void add_rms_kernel(const float* __restrict__ x,const float* __restrict__ r,
                               const float* __restrict__ w,float* __restrict__ res_out,
                               float* __restrict__ h_out,float* __restrict__ h_full){
    const int t = blockIdx.x, tid = threadIdx.x;
    const float4* xp = (const float4*)(x + (size_t)t*kH);
    const float4* rp = r ? (const float4*)(r + (size_t)t*kH) : nullptr;
    float4 v[2]; float ss = 0.f;
    #pragma unroll
    for (int i = 0; i < 2; i++) {
        int idx = tid + i*256;
        float4 a = xp[idx];
        if (rp) { float4 b = rp[idx]; a.x+=b.x; a.y+=b.y; a.z+=b.z; a.w+=b.w; }
        v[i] = a; ss += a.x*a.x + a.y*a.y + a.z*a.z + a.w*a.w;
    }
    __shared__ float sh[256];
    sh[tid] = ss; __syncthreads();
    for (int s = 128; s > 0; s >>= 1) { if (tid < s) sh[tid] += sh[tid+s]; __syncthreads(); }
    float scale = rsqrtf(sh[0]/(float)kH + kEPS);
    #pragma unroll
    for (int i = 0; i < 2; i++) {
        int idx = tid + i*256;
        if (res_out) ((float4*)(res_out + (size_t)t*kH))[idx] = v[i];
        float4 wv = ((const float4*)w)[idx];
        float4 hv = make_float4(v[i].x*scale*wv.x, v[i].y*scale*wv.y,
                                v[i].z*scale*wv.z, v[i].w*scale*wv.w);
        ((float4*)(h_out + (size_t)t*kH))[idx] =
            make_float4(rtf(hv.x), rtf(hv.y), rtf(hv.z), rtf(hv.w));
        if (h_full) ((float4*)(h_full + (size_t)t*kH))[idx] = hv;
    }
}

// fused: h = p0 + p1 + res_in (o-proj reduce absorbed), float4
__global__ void add_rms3_kernel(const float* __restrict__ p0,const float* __restrict__ p1,
                                const float* __restrict__ w,float* __restrict__ res_io,
                                float* __restrict__ h_out,float* __restrict__ h_full){
    const int t = blockIdx.x, tid = threadIdx.x;
    float4 v[2]; float ss = 0.f;
    #pragma unroll
    for (int i = 0; i < 2; i++) {
        int idx = tid + i*256;
        size_t o = (size_t)t*(kH/4) + idx;
        float4 a = ((const float4*)p0)[o];
        float4 b = ((const float4*)p1)[o];
        float4 c = ((const float4*)res_io)[o];
        float4 s4 = make_float4(a.x+b.x+c.x, a.y+b.y+c.y, a.z+b.z+c.z, a.w+b.w+c.w);
        v[i] = s4; ss += s4.x*s4.x + s4.y*s4.y + s4.z*s4.z + s4.w*s4.w;
    }
    __shared__ float sh[256];
    sh[tid] = ss; __syncthreads();
    for (int s = 128; s > 0; s >>= 1) { if (tid < s) sh[tid] += sh[tid+s]; __syncthreads(); }
    float scale = rsqrtf(sh[0]/(float)kH + kEPS);
    #pragma unroll
    for (int i = 0; i < 2; i++) {
        int idx = tid + i*256;
        size_t o = (size_t)t*(kH/4) + idx;
        ((float4*)res_io)[o] = v[i];
        float4 wv = ((const float4*)w)[idx];
        float4 hv = make_float4(v[i].x*scale*wv.x, v[i].y*scale*wv.y,
                                v[i].z*scale*wv.z, v[i].w*scale*wv.w);
        ((float4*)h_out)[o] = make_float4(rtf(hv.x), rtf(hv.y), rtf(hv.z), rtf(hv.w));
        if (h_full) ((float4*)h_full)[o] = hv;
    }
}

// ---------------- 128x128 GEMM; split factor = gridDim.z ----------------
__global__ void __launch_bounds__(256, 2)
gemm_splitk_kernel(const float* __restrict__ A,int lda,const float* __restrict__ B,int ldb,
                   float* __restrict__ Cpart,int ldc,int Kdim){
    extern __shared__ unsigned smem[];
    unsigned* As = smem;
    unsigned* Bs = smem + kStages*kABuf;
    const int row0 = blockIdx.x*128, col0 = blockIdx.y*128;
    const int Kpart = Kdim / gridDim.z;
    const int koff = blockIdx.z*Kpart;
    const int tid = threadIdx.x, lane = tid&31, warp = tid>>5;
    const int wm = (warp&1)*64, wn = (warp>>1)*32;
    const int g = lane>>2, t = lane&3;
    const float* Ab = A + (size_t)row0*lda + koff;
    const float* Bb = B + (size_t)koff*ldb + col0;
    float* C = Cpart + (size_t)blockIdx.z*kT*ldc;
    const int nk = Kpart >> 5;

    auto issue = [&](int s){
        unsigned* Ad = As + (s%kStages)*kABuf;
        unsigned* Bd = Bs + (s%kStages)*kBBuf;
        int kk0 = s*32;
        #pragma unroll
        for (int q = 0; q < 4; q++) {
            int e = tid + q*256;
            int m = e>>3, k4 = e&7;
            cp16(sptr(Ad + m*kSA + k4*4), Ab + (size_t)m*lda + kk0 + k4*4);
        }
        #pragma unroll
        for (int q = 0; q < 4; q++) {
            int e = tid + q*256;
            int k = e>>5, n16 = e&31;
            cp16(sptr(Bd + k*kSB + n16*4), Bb + (size_t)(kk0+k)*ldb + n16*4);
        }
        cp_commit();
    };
    for (int s = 0; s < kStages-1; s++) { if (s < nk) issue(s); else cp_commit(); }

    const unsigned aO = a_off(wm,lane);
    float acc[4][4][4] = {};
    for (int i = 0; i < nk; i++) {
        cp_wait1();
        __syncthreads();
        int s = i + kStages - 1;
        if (s < nk) issue(s); else cp_commit();
        compute_plain<true>(sptr(As + (i%kStages)*kABuf) + aO, Bs + (i%kStages)*kBBuf, wn, g, t, acc);
    }
    #pragma unroll
    for (int im = 0; im < 4; im++)
        #pragma unroll
        for (int jn = 0; jn < 4; jn++) {
            int r0 = row0 + wm + im*16 + g;
            int c0 = col0 + wn + jn*8 + 2*t;
            #pragma unroll
            for (int hh = 0; hh < 2; hh++) {
                int rr = r0 + hh*8;
                C[(size_t)rr*ldc + c0]   = acc[im][jn][hh*2+0];
                C[(size_t)rr*ldc + c0+1] = acc[im][jn][hh*2+1];
            }
        }
}

// ---------------- QK-RMSNorm + RoPE; fuses QKV split-K reduce ----------------
__global__ void rope_kernel(const int* __restrict__ positions,const float* __restrict__ q_norm_w,
                            const float* __restrict__ k_norm_w){
    const int t = blockIdx.x, hh = blockIdx.y, lane = threadIdx.x;
    const float* p0 = g_part;
    const float* p1 = g_part + (size_t)kT*kQKV;
    if (hh >= kNH + kNKV) {
        int vh = hh - kNH - kNKV;
        size_t o = (size_t)t*kQKV + (kNH+kNKV)*kHD + vh*kHD + lane;
        g_qkv[o] = rtf(p0[o] + p1[o]);
        return;
    }
    const size_t base = (size_t)t*kQKV + (hh < kNH ? hh*kHD : kNH*kHD + (hh-kNH)*kHD);
    const float* nw = (hh < kNH) ? q_norm_w : k_norm_w;
    float v = p0[base + lane] + p1[base + lane];
    __shared__ float sred[128];
    sred[lane] = v*v; __syncthreads();
    for (int s = 64; s > 0; s >>= 1) { if (lane < s) sred[lane] += sred[lane+s]; __syncthreads(); }
    float scale = rsqrtf(sred[0]/(float)kHD + kEPS);
    float xn = v*scale*nw[lane];
    __shared__ float sh[128];
    sh[lane] = xn; __syncthreads();
    int j = lane & 63;
    const float kLog2Theta_64 = 19.931568569324174f / 64.0f;
    float inv = exp2f(-(float)j * kLog2Theta_64);
    float ang = (float)positions[t] * inv;
    float s, c;
    sincosf(ang, &s, &c);
    float outv = (lane < 64) ? sh[lane]*c - sh[lane+64]*s : sh[lane]*c + sh[lane-64]*s;
    g_qkv[base + lane] = rtf(outv);
}

__global__ void __launch_bounds__(256,2) scores_kernel(){
    const int qt = blockIdx.x, kt = blockIdx.y, h = blockIdx.z;
    if (kt > qt) return;
    extern __shared__ unsigned smw[];
    unsigned* As = smw;
    unsigned* Bst = smw + kStages*kABuf;
    const float* Q  = g_qkv + (size_t)qt*128*kQKV + h*kHD;
    const float* Kp = g_qkv + (size_t)kt*128*kQKV + kNH*kHD + (h>>2)*kHD;
    const int tid = threadIdx.x, lane = tid&31, warp = tid>>5;
    const int wm = (warp&1)*64, wn = (warp>>1)*32;
    const int g = lane>>2, t = lane&3;
    const int nk = kHD >> 5;
    auto issue = [&](int s){
        unsigned* Ad = As + (s%kStages)*kABuf;
        unsigned* Bd = Bst + (s%kStages)*kABuf;
        int kk0 = s*32;
        #pragma unroll
        for (int q = 0; q < 4; q++) {
            int e = tid + q*256;
            int m = e>>3, k4 = e&7;
            cp16(sptr(Ad + m*kSA + k4*4), Q  + (size_t)m*kQKV + kk0 + k4*4);
            cp16(sptr(Bd + m*kSA + k4*4), Kp + (size_t)m*kQKV + kk0 + k4*4);
        }
        cp_commit();
    };
    for (int s = 0; s < kStages-1; s++) { if (s < nk) issue(s); else cp_commit(); }
    const unsigned aO = a_off(wm,lane), b0 = b_off(wn,0,lane), b1 = b_off(wn,1,lane);
    float acc[4][4][4] = {};
    for (int i = 0; i < nk; i++) {
        cp_wait1();
        __syncthreads();
        int s = i + kStages - 1;
        if (s < nk) issue(s); else cp_commit();
        int p = i % kStages;
        compute_tt(sptr(As+p*kABuf)+aO, sptr(Bst+p*kABuf)+b0, sptr(Bst+p*kABuf)+b1, acc);
    }
    const int row0 = qt*128, col0 = kt*128;
    #pragma unroll
    for (int im = 0; im < 4; im++)
        #pragma unroll
        for (int jn = 0; jn < 4; jn++) {
            int r0 = row0 + wm + im*16 + g;
            int c0 = col0 + wn + jn*8 + 2*t;
            #pragma unroll
            for (int hh = 0; hh < 2; hh++) {
                int qi = r0 + hh*8;
                float v0 = acc[im][jn][hh*2+0]*kScale;
                float v1 = acc[im][jn][hh*2+1]*kScale;
                if (c0   > qi) v0 = -1e9f;
                if (c0+1 > qi) v1 = -1e9f;
                g_scores[((size_t)h*kT+qi)*kT + c0]   = v0;
                g_scores[((size_t)h*kT+qi)*kT + c0+1] = v1;
            }
        }
}

// ---------------- row softmax, float4 ----------------
__global__ void softmax_kernel(){
    const int q = blockIdx.x, h = blockIdx.y, tid = threadIdx.x;
    float4* row4 = (float4*)(g_scores + ((size_t)h*kT + q)*kT);
    const int n4 = ((q>>7)+1) << 5;
    __shared__ float sh[256];
    float lmax = -3.4e38f;
    for (int i = tid; i < n4; i += 256) {
        float4 v = row4[i];
        lmax = fmaxf(lmax, fmaxf(fmaxf(v.x, v.y), fmaxf(v.z, v.w)));
    }
    sh[tid] = lmax; __syncthreads();
    for (int s = 128; s > 0; s >>= 1) { if (tid < s) sh[tid] = fmaxf(sh[tid], sh[tid+s]); __syncthreads(); }
    float m = sh[0]; __syncthreads();
    float lsum = 0.f;
    for (int i = tid; i < n4; i += 256) {
        float4 v = row4[i];
        v.x = __expf(v.x - m); v.y = __expf(v.y - m);
        v.z = __expf(v.z - m); v.w = __expf(v.w - m);
        row4[i] = v;
        lsum += v.x + v.y + v.z + v.w;
    }
    sh[tid] = lsum; __syncthreads();
    for (int s = 128; s > 0; s >>= 1) { if (tid < s) sh[tid] += sh[tid+s]; __syncthreads(); }
    float inv = 1.f/sh[0];
    for (int i = tid; i < n4; i += 256) {
        float4 v = row4[i];
        row4[i] = make_float4(rtf(v.x*inv), rtf(v.y*inv), rtf(v.z*inv), rtf(v.w*inv));
    }
}

__global__ void __launch_bounds__(256,2) pv_kernel(){
    const int qt = blockIdx.x, h = blockIdx.y;
    extern __shared__ unsigned smw[];
    unsigned* As = smw;
    unsigned* Bs = smw + kStages*kABuf;
    const int row0 = qt*128;
    const int Kdim = (qt+1)*128;
    const float* A = g_scores + ((size_t)h*kT + row0)*kT;
    const float* B = g_qkv + (kNH+kNKV)*kHD + (h>>2)*kHD;
    const int tid = threadIdx.x, lane = tid&31, warp = tid>>5;
    const int wm = (warp&1)*64, wn = (warp>>1)*32;
    const int g = lane>>2, t = lane&3;
    const int nk = Kdim >> 5;
    auto issue = [&](int s){
        unsigned* Ad = As + (s%kStages)*kABuf;
        unsigned* Bd = Bs + (s%kStages)*kBBuf;
        int kk0 = s*32;
        #pragma unroll
        for (int q = 0; q < 4; q++) {
            int e = tid + q*256;
            int m = e>>3, k4 = e&7;
            cp16(sptr(Ad + m*kSA + k4*4), A + (size_t)m*kT + kk0 + k4*4);
        }
        #pragma unroll
        for (int q = 0; q < 4; q++) {
            int e = tid + q*256;
            int k = e>>5, n16 = e&31;
            cp16(sptr(Bd + k*kSB + n16*4), B + (size_t)(kk0+k)*kQKV + n16*4);
        }
        cp_commit();
    };
    for (int s = 0; s < kStages-1; s++) { if (s < nk) issue(s); else cp_commit(); }
    const unsigned aO = a_off(wm,lane);
    float acc[4][4][4] = {};
    for (int i = 0; i < nk; i++) {
        cp_wait1();
        __syncthreads();
        int s = i + kStages - 1;
        if (s < nk) issue(s); else cp_commit();
        int p = i % kStages;
        compute_plain<false>(sptr(As+p*kABuf)+aO, Bs+p*kBBuf, wn, g, t, acc);
    }
    #pragma unroll
    for (int im = 0; im < 4; im++)
        #pragma unroll
        for (int jn = 0; jn < 4; jn++) {
            int r0 = row0 + wm + im*16 + g;
            int c0 = wn + jn*8 + 2*t;
            #pragma unroll
            for (int hh = 0; hh < 2; hh++) {
                int rr = r0 + hh*8;
                g_attn[(size_t)rr*kH + h*kHD + c0]   = rtf(acc[im][jn][hh*2+0]);
                g_attn[(size_t)rr*kH + h*kHD + c0+1] = rtf(acc[im][jn][hh*2+1]);
            }
        }
}

__global__ void router_kernel(const float* __restrict__ gate_w){
    const int t = blockIdx.x, tid = threadIdx.x;
    const float* hp = g_h2f + (size_t)t*kH;
    float acc[kE] = {};
    for (int k = tid; k < kH; k += 256) {
        float hv = hp[k];
        const float* gw = gate_w + (size_t)k*kE;
        #pragma unroll
        for (int e = 0; e < kE; e++) acc[e] += hv*gw[e];
    }
    __shared__ float sh[kE][256];
    #pragma unroll
    for (int e = 0; e < kE; e++) sh[e][tid] = acc[e];
    __syncthreads();
    for (int s = 128; s > 0; s >>= 1) {
        if (tid < s) {
            #pragma unroll
            for (int e = 0; e < kE; e++) sh[e][tid] += sh[e][tid+s];
        }
        __syncthreads();
    }
    if (tid == 0) {
        float l[kE], mx = -3.4e38f;
        #pragma unroll
        for (int e = 0; e < kE; e++) { l[e] = sh[e][0]; mx = fmaxf(mx, l[e]); }
        float sum = 0.f;
        #pragma unroll
        for (int e = 0; e < kE; e++) { l[e] = __expf(l[e]-mx); sum += l[e]; }
        float isum = 1.f/sum;
        float best = -1.f, second = -1.f; int bi = 0, si = 0;
        #pragma unroll
        for (int e = 0; e < kE; e++) {
            float p = l[e]*isum;
            if (p > best) { second = best; si = bi; best = p; bi = e; }
            else if (p > second) { second = p; si = e; }
        }
        float denom = 1.f/(best + second);
        g_topi[t*2]   = bi; g_topw[t*2]   = best*denom;
        g_topi[t*2+1] = si; g_topw[t*2+1] = second*denom;
        atomicAdd(&g_cnt[bi], 1);
        atomicAdd(&g_cnt[si], 1);
    }
}

__global__ void moe_init_kernel(){
    int i = blockIdx.x*256 + threadIdx.x;
    if (i < kE) g_cnt[i] = 0;
    if (i < kSlots) g_tok[i] = kT;
    if (i < kH) g_h2[(size_t)kT*kH + i] = 0.f;
}
__global__ void moe_setup_kernel(){
    int off = 0, tile = 0;
    for (int e = 0; e < kE; e++) {
        g_cursor[e] = off;
        int seg = ((g_cnt[e] + 127)/128)*128;
        for (int i = 0; i < seg/128; i++) g_tile_e[tile++] = e;
        off += seg;
    }
    g_ntiles = tile;
}
__global__ void moe_scatter_kernel(){
    int t = blockIdx.x*256 + threadIdx.x;
    if (t >= kT) return;
    #pragma unroll
    for (int k = 0; k < 2; k++) {
        int e = g_topi[t*2+k];
        int pos = atomicAdd(&g_cursor[e], 1);
        g_tok[pos] = t;
        g_wt[pos]  = g_topw[t*2+k];
        g_slot_of[t*2+k] = pos;
    }
}

__global__ void __launch_bounds__(256,2) moe_gu_kernel(const float* __restrict__ w_gate_up){
    const int tile = blockIdx.x;
    if (tile >= g_ntiles) return;
    extern __shared__ unsigned smw[];
    unsigned* As = smw;
    unsigned* Bs = smw + kStages*kABuf;
    __shared__ int rows[128];
    const int tid = threadIdx.x;
    if (tid < 128) rows[tid] = g_tok[tile*128 + tid];
    __syncthreads();
    const int e = g_tile_e[tile];
    const int col0 = blockIdx.y*128;
    const float* Bb = w_gate_up + (size_t)e*kH*2*kI + col0;
    const int lane = tid&31, warp = tid>>5;
    const int wm = (warp&1)*64, wn = (warp>>1)*32;
    const int g = lane>>2, t = lane&3;
    const int nk = kH >> 5;
    auto issue = [&](int s){
        unsigned* Ad = As + (s%kStages)*kABuf;
        unsigned* Bd = Bs + (s%kStages)*kBBuf;
        int kk0 = s*32;
        #pragma unroll
        for (int q = 0; q < 4; q++) {
            int ee = tid + q*256;
            int m = ee>>3, k4 = ee&7;
            cp16(sptr(Ad + m*kSA + k4*4), g_h2 + (size_t)rows[m]*kH + kk0 + k4*4);
        }
        #pragma unroll
        for (int q = 0; q < 4; q++) {
            int ee = tid + q*256;
            int k = ee>>5, n16 = ee&31;
            cp16(sptr(Bd + k*kSB + n16*4), Bb + (size_t)(kk0+k)*(2*kI) + n16*4);
        }
        cp_commit();
    };
    for (int s = 0; s < kStages-1; s++) { if (s < nk) issue(s); else cp_commit(); }
    const unsigned aO = a_off(wm,lane);
    float acc[4][4][4] = {};
    for (int i = 0; i < nk; i++) {
        cp_wait1();
        __syncthreads();
        int s = i + kStages - 1;
        if (s < nk) issue(s); else cp_commit();
        int p = i % kStages;
        compute_plain<true>(sptr(As+p*kABuf)+aO, Bs+p*kBBuf, wn, g, t, acc);
    }
    #pragma unroll
    for (int im = 0; im < 4; im++)
        #pragma unroll
        for (int jn = 0; jn < 4; jn++) {
            int r0 = wm + im*16 + g;
            int c0 = col0 + wn + jn*8 + 2*t;
            #pragma unroll
            for (int hh = 0; hh < 2; hh++) {
                int slot = tile*128 + r0 + hh*8;
                g_gu[(size_t)slot*2*kI + c0]   = acc[im][jn][hh*2+0];
                g_gu[(size_t)slot*2*kI + c0+1] = acc[im][jn][hh*2+1];
            }
        }
}

__global__ void silu_kernel(){
    int idx = blockIdx.x*256 + threadIdx.x;
    int slot = idx / (kI/4), j4 = idx % (kI/4);
    if (slot >= g_ntiles*128) return;
    float4 gv = ((const float4*)(g_gu + (size_t)slot*2*kI))[j4];
    float4 uv = ((const float4*)(g_gu + (size_t)slot*2*kI + kI))[j4];
    float4 o;
    o.x = rtf((gv.x / (1.f + __expf(-gv.x))) * uv.x);
    o.y = rtf((gv.y / (1.f + __expf(-gv.y))) * uv.y);
    o.z = rtf((gv.z / (1.f + __expf(-gv.z))) * uv.z);
    o.w = rtf((gv.w / (1.f + __expf(-gv.w))) * uv.w);
    ((float4*)(g_act))[(size_t)slot*(kI/4) + j4] = o;
}

__global__ void __launch_bounds__(256,2) moe_down_kernel(const float* __restrict__ w_down){
    const int tile = blockIdx.x;
    if (tile >= g_ntiles) return;
    extern __shared__ unsigned smw[];
    unsigned* As = smw;
    unsigned* Bs = smw + kStages*kABuf;
    const int e = g_tile_e[tile];
    const int col0 = blockIdx.y*128;
    const float* A  = g_act + (size_t)tile*128*kI;
    const float* Bb = w_down + (size_t)e*kI*kH + col0;
    const int tid = threadIdx.x, lane = tid&31, warp = tid>>5;
    const int wm = (warp&1)*64, wn = (warp>>1)*32;
    const int g = lane>>2, t = lane&3;
    const int nk = kI >> 5;
    auto issue = [&](int s){
        unsigned* Ad = As + (s%kStages)*kABuf;
        unsigned* Bd = Bs + (s%kStages)*kBBuf;
        int kk0 = s*32;
        #pragma unroll
        for (int q = 0; q < 4; q++) {
            int ee = tid + q*256;
            int m = ee>>3, k4 = ee&7;
            cp16(sptr(Ad + m*kSA + k4*4), A + (size_t)m*kI + kk0 + k4*4);
        }
        #pragma unroll
        for (int q = 0; q < 4; q++) {
            int ee = tid + q*256;
            int k = ee>>5, n16 = ee&31;
            cp16(sptr(Bd + k*kSB + n16*4), Bb + (size_t)(kk0+k)*kH + n16*4);
        }
        cp_commit();
    };
    for (int s = 0; s < kStages-1; s++) { if (s < nk) issue(s); else cp_commit(); }
    const unsigned aO = a_off(wm,lane);
    float acc[4][4][4] = {};
    for (int i = 0; i < nk; i++) {
        cp_wait1();
        __syncthreads();
        int s = i + kStages - 1;
        if (s < nk) issue(s); else cp_commit();
        int p = i % kStages;
        compute_plain<true>(sptr(As+p*kABuf)+aO, Bs+p*kBBuf, wn, g, t, acc);
    }
    #pragma unroll
    for (int im = 0; im < 4; im++)
        #pragma unroll
        for (int jn = 0; jn < 4; jn++) {
            int r0 = wm + im*16 + g;
            int c0 = col0 + wn + jn*8 + 2*t;
            #pragma unroll
            for (int hh = 0; hh < 2; hh++) {
                int slot = tile*128 + r0 + hh*8;
                g_ds[(size_t)slot*kH + c0]   = acc[im][jn][hh*2+0];
                g_ds[(size_t)slot*kH + c0+1] = acc[im][jn][hh*2+1];
            }
        }
}

__global__ void combine_kernel(float* __restrict__ out){
    const int t = blockIdx.x;
    const int s0 = g_slot_of[t*2], s1 = g_slot_of[t*2+1];
    const float w0 = g_wt[s0], w1 = g_wt[s1];
    const float4* d0 = (const float4*)(g_ds + (size_t)s0*kH);
    const float4* d1 = (const float4*)(g_ds + (size_t)s1*kH);
    float4* o = (float4*)(out + (size_t)t*kH);
    for (int j = threadIdx.x; j < kH/4; j += 256) {
        float4 a = d0[j], b = d1[j];
        o[j] = make_float4(w0*a.x + w1*b.x, w0*a.y + w1*b.y,
                           w0*a.z + w1*b.z, w0*a.w + w1*b.w);
    }
}

extern "C" void kernel_launch(void* const* d_in, const int* in_sizes, int n_in,
                              void* d_out, int out_size) {
    const int*   positions = (const int*)  d_in[0];
    const float* hidden    = (const float*)d_in[1];
    const float* residual  = (const float*)d_in[2];
    const float* w_qkv     = (const float*)d_in[3];
    const float* w_o       = (const float*)d_in[4];
    const float* q_norm_w  = (const float*)d_in[5];
    const float* k_norm_w  = (const float*)d_in[6];
    const float* ln1_w     = (const float*)d_in[7];
    const float* ln2_w     = (const float*)d_in[8];
    const float* gate_w    = (const float*)d_in[9];
    const float* w_gate_up = (const float*)d_in[10];
    const float* w_down    = (const float*)d_in[11];
    float* out = (float*)d_out;
    float* res = out + (size_t)kT*kH;

    float* d_h1;   cudaGetSymbolAddress((void**)&d_h1,  g_h1);
    float* d_part; cudaGetSymbolAddress((void**)&d_part,g_part);
    float* d_attn; cudaGetSymbolAddress((void**)&d_attn,g_attn);
    float* d_h2;   cudaGetSymbolAddress((void**)&d_h2,  g_h2);
    float* d_h2f;  cudaGetSymbolAddress((void**)&d_h2f, g_h2f);

    cudaFuncSetAttribute(gemm_splitk_kernel, cudaFuncAttributeMaxDynamicSharedMemorySize, (int)kPlainSmem);
    cudaFuncSetAttribute(scores_kernel,      cudaFuncAttributeMaxDynamicSharedMemorySize, (int)kTTSmem);
    cudaFuncSetAttribute(pv_kernel,          cudaFuncAttributeMaxDynamicSharedMemorySize, (int)kPlainSmem);
    cudaFuncSetAttribute(moe_gu_kernel,      cudaFuncAttributeMaxDynamicSharedMemorySize, (int)kPlainSmem);
    cudaFuncSetAttribute(moe_down_kernel,    cudaFuncAttributeMaxDynamicSharedMemorySize, (int)kPlainSmem);

    add_rms_kernel<<<kT, 256>>>(hidden, residual, ln1_w, res, d_h1, nullptr);
    // QKV: split-K2 -> partials; reduce fused into rope
    gemm_splitk_kernel<<<dim3(kT/128, kQKV/128, 2), 256, kPlainSmem>>>(d_h1, kH, w_qkv, kQKV, d_part, kQKV, kH);
    rope_kernel<<<dim3(kT, kNH + 2*kNKV), 128>>>(positions, q_norm_w, k_norm_w);
    scores_kernel<<<dim3(kT/128, kT/128, kNH), 256, kTTSmem>>>();
    softmax_kernel<<<dim3(kT, kNH), 256>>>();
    pv_kernel<<<dim3(kT/128, kNH), 256, kPlainSmem>>>();
    // O-proj: split-K2 -> partials; reduce fused into add_rms3
    gemm_splitk_kernel<<<dim3(kT/128, kH/128, 2), 256, kPlainSmem>>>(d_attn, kH, w_o, kH, d_part, kH, kH);
    add_rms3_kernel<<<kT, 256>>>(d_part, d_part + (size_t)kT*kH, ln2_w, res, d_h2, d_h2f);
    moe_init_kernel<<<(kSlots + 255)/256, 256>>>();
    router_kernel<<<kT, 256>>>(gate_w);
    moe_setup_kernel<<<1, 1>>>();
    moe_scatter_kernel<<<(kT + 255)/256, 256>>>();
    moe_gu_kernel<<<dim3(kTiles, 2*kI/128), 256, kPlainSmem>>>(w_gate_up);
    silu_kernel<<<(kSlots*(kI/4) + 255)/256, 256>>>();
    moe_down_kernel<<<dim3(kTiles, kH/128), 256, kPlainSmem>>>(w_down);
    combine_kernel<<<kT, 256>>>(out);
}

// round 16
// speedup vs baseline: 1.0887x; 1.0397x over previous
#include <cuda_runtime.h>
#include <math.h>

constexpr int kT=1024, kH=2048, kNH=16, kNKV=4, kHD=128, kE=8, kI=768;
constexpr int kQKV = kNH*kHD + 2*kNKV*kHD;
constexpr float kEPS=1e-6f, kScale=0.08838834764831845f;
constexpr int kSlots=3072, kTiles=kSlots/128, kStages=3;

__device__ float g_h1[kT*kH];
__device__ float g_qkv[kT*kQKV];
__device__ float g_part[2*kT*kQKV];
__device__ float g_scores[(size_t)kNH*kT*kT];   // also reused as MoE split-K partial buffer
__device__ float g_attn[kT*kH];
__device__ float g_h2[(kT+1)*kH];
__device__ float g_h2f[kT*kH];
__device__ float g_act[(size_t)kSlots*kI];
__device__ int   g_tok[kSlots];
__device__ float g_wt[kSlots];
__device__ int   g_slot_of[kT*2];
__device__ int   g_topi[kT*2];
__device__ float g_topw[kT*2];
__device__ int   g_cnt[kE];
__device__ int   g_cursor[kE];
__device__ int   g_tile_e[kTiles];
__device__ int   g_ntiles;

__device__ __forceinline__ unsigned f2tf(float x){unsigned r;asm("cvt.rna.tf32.f32 %0, %1;":"=r"(r):"f"(x));return r;}
__device__ __forceinline__ float rtf(float x){return __uint_as_float(f2tf(x));}
__device__ __forceinline__ void mma_tf32(float c[4],unsigned a0,unsigned a1,unsigned a2,unsigned a3,unsigned b0,unsigned b1){
    asm volatile("mma.sync.aligned.m16n8k8.row.col.f32.tf32.tf32.f32 {%0,%1,%2,%3}, {%4,%5,%6,%7}, {%8,%9}, {%0,%1,%2,%3};"
                 :"+f"(c[0]),"+f"(c[1]),"+f"(c[2]),"+f"(c[3]):"r"(a0),"r"(a1),"r"(a2),"r"(a3),"r"(b0),"r"(b1));
}
__device__ __forceinline__ unsigned sptr(const void* p){return (unsigned)__cvta_generic_to_shared(p);}
__device__ __forceinline__ void cp16(unsigned d,const void* s){asm volatile("cp.async.cg.shared.global [%0], [%1], 16;"::"r"(d),"l"(s));}
__device__ __forceinline__ void cp_commit(){asm volatile("cp.async.commit_group;");}
__device__ __forceinline__ void cp_wait1(){asm volatile("cp.async.wait_group 1;");}
__device__ __forceinline__ void ldsm4(unsigned&r0,unsigned&r1,unsigned&r2,unsigned&r3,unsigned a){
    asm volatile("ldmatrix.sync.aligned.m8n8.x4.shared.b16 {%0,%1,%2,%3}, [%4];":"=r"(r0),"=r"(r1),"=r"(r2),"=r"(r3):"r"(a));
}

constexpr int kSA=36, kSB=136, kABuf=128*kSA, kBBuf=32*kSB;
constexpr size_t kPlainSmem=(size_t)kStages*(kABuf+kBBuf)*4;
constexpr size_t kTTSmem=(size_t)kStages*2*kABuf*4;

__device__ __forceinline__ unsigned a_off(int wm,int lane){
    int sub=lane>>3, lr=lane&7;
    return 4u*((wm+(sub&1)*8+lr)*kSA + (sub>>1)*4);
}
__device__ __forceinline__ unsigned b_off(int wn,int p,int lane){
    int sub=lane>>3, lr=lane&7;
    return 4u*((wn+p*16+(sub>>1)*8+lr)*kSA + (sub&1)*4);
}
template <bool DoCvt>
__device__ __forceinline__ void compute_plain(unsigned aB,const unsigned* __restrict__ Bc,int wn,int g,int t,float acc[4][4][4]){
    #pragma unroll
    for (int kk = 0; kk < 32; kk += 8) {
        unsigned a[4][4], b[4][2];
        #pragma unroll
        for (int im = 0; im < 4; im++) ldsm4(a[im][0],a[im][1],a[im][2],a[im][3], aB+4u*(im*16*kSA+kk));
        #pragma unroll
        for (int jn = 0; jn < 4; jn++) {
            unsigned b0 = Bc[(kk+t)*kSB+wn+jn*8+g];
            unsigned b1 = Bc[(kk+t+4)*kSB+wn+jn*8+g];
            if (DoCvt) { b[jn][0]=f2tf(__uint_as_float(b0)); b[jn][1]=f2tf(__uint_as_float(b1)); }
            else       { b[jn][0]=b0; b[jn][1]=b1; }
        }
        #pragma unroll
        for (int im = 0; im < 4; im++)
            #pragma unroll
            for (int jn = 0; jn < 4; jn++)
                mma_tf32(acc[im][jn],a[im][0],a[im][1],a[im][2],a[im][3],b[jn][0],b[jn][1]);
    }
}
__device__ __forceinline__ void compute_tt(unsigned aB,unsigned b0a,unsigned b1a,float acc[4][4][4]){
    #pragma unroll
    for (int kk = 0; kk < 32; kk += 8) {
        unsigned a[4][4], b[4][2];
        #pragma unroll
        for (int im = 0; im < 4; im++) ldsm4(a[im][0],a[im][1],a[im][2],a[im][3], aB+4u*(im*16*kSA+kk));
        ldsm4(b[0][0],b[0][1],b[1][0],b[1][1], b0a+4u*kk);
        ldsm4(b[2][0],b[2][1],b[3][0],b[3][1], b1a+4u*kk);
        #pragma unroll
        for (int im = 0; im < 4; im++)
            #pragma unroll
            for (int jn = 0; jn < 4; jn++)
                mma_tf32(acc[im][jn],a[im][0],a[im][1],a[im][2],a[im][3],b[jn][0],b[jn][1]);
    }
}

__global__ void add_rms_kernel(const float* __restrict__ x,const float* __restrict__ r,
                               const float* __restrict__ w,float* __restrict__ res_out,
                               float* __restrict__ h_out,float* __restrict__ h_full){
    const int t = blockIdx.x, tid = threadIdx.x;
    const float4* xp = (const float4*)(x + (size_t)t*kH);
    const float4* rp = r ? (const float4*)(r + (size_t)t*kH) : nullptr;
    float4 v[2]; float ss = 0.f;
    #pragma unroll
    for (int i = 0; i < 2; i++) {
        int idx = tid + i*256;
        float4 a = xp[idx];
        if (rp) { float4 b = rp[idx]; a.x+=b.x; a.y+=b.y; a.z+=b.z; a.w+=b.w; }
        v[i] = a; ss += a.x*a.x + a.y*a.y + a.z*a.z + a.w*a.w;
    }
    __shared__ float sh[256];
    sh[tid] = ss; __syncthreads();
    for (int s = 128; s > 0; s >>= 1) { if (tid < s) sh[tid] += sh[tid+s]; __syncthreads(); }
    float scale = rsqrtf(sh[0]/(float)kH + kEPS);
    #pragma unroll
    for (int i = 0; i < 2; i++) {
        int idx = tid + i*256;
        if (res_out) ((float4*)(res_out + (size_t)t*kH))[idx] = v[i];
        float4 wv = ((const float4*)w)[idx];
        float4 hv = make_float4(v[i].x*scale*wv.x, v[i].y*scale*wv.y,
                                v[i].z*scale*wv.z, v[i].w*scale*wv.w);
        ((float4*)(h_out + (size_t)t*kH))[idx] =
            make_float4(rtf(hv.x), rtf(hv.y), rtf(hv.z), rtf(hv.w));
        if (h_full) ((float4*)(h_full + (size_t)t*kH))[idx] = hv;
    }
}

__global__ void add_rms3_kernel(const float* __restrict__ p0,const float* __restrict__ p1,
                                const float* __restrict__ w,float* __restrict__ res_io,
                                float* __restrict__ h_out,float* __restrict__ h_full){
    const int t = blockIdx.x, tid = threadIdx.x;
    float4 v[2]; float ss = 0.f;
    #pragma unroll
    for (int i = 0; i < 2; i++) {
        int idx = tid + i*256;
        size_t o = (size_t)t*(kH/4) + idx;
        float4 a = ((const float4*)p0)[o];
        float4 b = ((const float4*)p1)[o];
        float4 c = ((const float4*)res_io)[o];
        float4 s4 = make_float4(a.x+b.x+c.x, a.y+b.y+c.y, a.z+b.z+c.z, a.w+b.w+c.w);
        v[i] = s4; ss += s4.x*s4.x + s4.y*s4.y + s4.z*s4.z + s4.w*s4.w;
    }
    __shared__ float sh[256];
    sh[tid] = ss; __syncthreads();
    for (int s = 128; s > 0; s >>= 1) { if (tid < s) sh[tid] += sh[tid+s]; __syncthreads(); }
    float scale = rsqrtf(sh[0]/(float)kH + kEPS);
    #pragma unroll
    for (int i = 0; i < 2; i++) {
        int idx = tid + i*256;
        size_t o = (size_t)t*(kH/4) + idx;
        ((float4*)res_io)[o] = v[i];
        float4 wv = ((const float4*)w)[idx];
        float4 hv = make_float4(v[i].x*scale*wv.x, v[i].y*scale*wv.y,
                                v[i].z*scale*wv.z, v[i].w*scale*wv.w);
        ((float4*)h_out)[o] = make_float4(rtf(hv.x), rtf(hv.y), rtf(hv.z), rtf(hv.w));
        if (h_full) ((float4*)h_full)[o] = hv;
    }
}

// ---------------- 128x128 GEMM; split factor = gridDim.z ----------------
__global__ void __launch_bounds__(256, 2)
gemm_splitk_kernel(const float* __restrict__ A,int lda,const float* __restrict__ B,int ldb,
                   float* __restrict__ Cpart,int ldc,int Kdim){
    extern __shared__ unsigned smem[];
    unsigned* As = smem;
    unsigned* Bs = smem + kStages*kABuf;
    const int row0 = blockIdx.x*128, col0 = blockIdx.y*128;
    const int Kpart = Kdim / gridDim.z;
    const int koff = blockIdx.z*Kpart;
    const int tid = threadIdx.x, lane = tid&31, warp = tid>>5;
    const int wm = (warp&1)*64, wn = (warp>>1)*32;
    const int g = lane>>2, t = lane&3;
    const float* Ab = A + (size_t)row0*lda + koff;
    const float* Bb = B + (size_t)koff*ldb + col0;
    float* C = Cpart + (size_t)blockIdx.z*kT*ldc;
    const int nk = Kpart >> 5;

    auto issue = [&](int s){
        unsigned* Ad = As + (s%kStages)*kABuf;
        unsigned* Bd = Bs + (s%kStages)*kBBuf;
        int kk0 = s*32;
        #pragma unroll
        for (int q = 0; q < 4; q++) {
            int e = tid + q*256;
            int m = e>>3, k4 = e&7;
            cp16(sptr(Ad + m*kSA + k4*4), Ab + (size_t)m*lda + kk0 + k4*4);
        }
        #pragma unroll
        for (int q = 0; q < 4; q++) {
            int e = tid + q*256;
            int k = e>>5, n16 = e&31;
            cp16(sptr(Bd + k*kSB + n16*4), Bb + (size_t)(kk0+k)*ldb + n16*4);
        }
        cp_commit();
    };
    for (int s = 0; s < kStages-1; s++) { if (s < nk) issue(s); else cp_commit(); }

    const unsigned aO = a_off(wm,lane);
    float acc[4][4][4] = {};
    for (int i = 0; i < nk; i++) {
        cp_wait1();
        __syncthreads();
        int s = i + kStages - 1;
        if (s < nk) issue(s); else cp_commit();
        compute_plain<true>(sptr(As + (i%kStages)*kABuf) + aO, Bs + (i%kStages)*kBBuf, wn, g, t, acc);
    }
    #pragma unroll
    for (int im = 0; im < 4; im++)
        #pragma unroll
        for (int jn = 0; jn < 4; jn++) {
            int r0 = row0 + wm + im*16 + g;
            int c0 = col0 + wn + jn*8 + 2*t;
            #pragma unroll
            for (int hh = 0; hh < 2; hh++) {
                int rr = r0 + hh*8;
                C[(size_t)rr*ldc + c0]   = acc[im][jn][hh*2+0];
                C[(size_t)rr*ldc + c0+1] = acc[im][jn][hh*2+1];
            }
        }
}

// ---------------- QK-RMSNorm + RoPE; fuses QKV split-K reduce ----------------
__global__ void rope_kernel(const int* __restrict__ positions,const float* __restrict__ q_norm_w,
                            const float* __restrict__ k_norm_w){
    const int t = blockIdx.x, hh = blockIdx.y, lane = threadIdx.x;
    const float* p0 = g_part;
    const float* p1 = g_part + (size_t)kT*kQKV;
    if (hh >= kNH + kNKV) {
        int vh = hh - kNH - kNKV;
        size_t o = (size_t)t*kQKV + (kNH+kNKV)*kHD + vh*kHD + lane;
        g_qkv[o] = rtf(p0[o] + p1[o]);
        return;
    }
    const size_t base = (size_t)t*kQKV + (hh < kNH ? hh*kHD : kNH*kHD + (hh-kNH)*kHD);
    const float* nw = (hh < kNH) ? q_norm_w : k_norm_w;
    float v = p0[base + lane] + p1[base + lane];
    __shared__ float sred[128];
    sred[lane] = v*v; __syncthreads();
    for (int s = 64; s > 0; s >>= 1) { if (lane < s) sred[lane] += sred[lane+s]; __syncthreads(); }
    float scale = rsqrtf(sred[0]/(float)kHD + kEPS);
    float xn = v*scale*nw[lane];
    __shared__ float sh[128];
    sh[lane] = xn; __syncthreads();
    int j = lane & 63;
    const float kLog2Theta_64 = 19.931568569324174f / 64.0f;
    float inv = exp2f(-(float)j * kLog2Theta_64);
    float ang = (float)positions[t] * inv;
    float s, c;
    sincosf(ang, &s, &c);
    float outv = (lane < 64) ? sh[lane]*c - sh[lane+64]*s : sh[lane]*c + sh[lane-64]*s;
    g_qkv[base + lane] = rtf(outv);
}

__global__ void __launch_bounds__(256,2) scores_kernel(){
    const int qt = blockIdx.x, kt = blockIdx.y, h = blockIdx.z;
    if (kt > qt) return;
    extern __shared__ unsigned smw[];
    unsigned* As = smw;
    unsigned* Bst = smw + kStages*kABuf;
    const float* Q  = g_qkv + (size_t)qt*128*kQKV + h*kHD;
    const float* Kp = g_qkv + (size_t)kt*128*kQKV + kNH*kHD + (h>>2)*kHD;
    const int tid = threadIdx.x, lane = tid&31, warp = tid>>5;
    const int wm = (warp&1)*64, wn = (warp>>1)*32;
    const int g = lane>>2, t = lane&3;
    const int nk = kHD >> 5;
    auto issue = [&](int s){
        unsigned* Ad = As + (s%kStages)*kABuf;
        unsigned* Bd = Bst + (s%kStages)*kABuf;
        int kk0 = s*32;
        #pragma unroll
        for (int q = 0; q < 4; q++) {
            int e = tid + q*256;
            int m = e>>3, k4 = e&7;
            cp16(sptr(Ad + m*kSA + k4*4), Q  + (size_t)m*kQKV + kk0 + k4*4);
            cp16(sptr(Bd + m*kSA + k4*4), Kp + (size_t)m*kQKV + kk0 + k4*4);
        }
        cp_commit();
    };
    for (int s = 0; s < kStages-1; s++) { if (s < nk) issue(s); else cp_commit(); }
    const unsigned aO = a_off(wm,lane), b0 = b_off(wn,0,lane), b1 = b_off(wn,1,lane);
    float acc[4][4][4] = {};
    for (int i = 0; i < nk; i++) {
        cp_wait1();
        __syncthreads();
        int s = i + kStages - 1;
        if (s < nk) issue(s); else cp_commit();
        int p = i % kStages;
        compute_tt(sptr(As+p*kABuf)+aO, sptr(Bst+p*kABuf)+b0, sptr(Bst+p*kABuf)+b1, acc);
    }
    const int row0 = qt*128, col0 = kt*128;
    #pragma unroll
    for (int im = 0; im < 4; im++)
        #pragma unroll
        for (int jn = 0; jn < 4; jn++) {
            int r0 = row0 + wm + im*16 + g;
            int c0 = col0 + wn + jn*8 + 2*t;
            #pragma unroll
            for (int hh = 0; hh < 2; hh++) {
                int qi = r0 + hh*8;
                float v0 = acc[im][jn][hh*2+0]*kScale;
                float v1 = acc[im][jn][hh*2+1]*kScale;
                if (c0   > qi) v0 = -1e9f;
                if (c0+1 > qi) v1 = -1e9f;
                g_scores[((size_t)h*kT+qi)*kT + c0]   = v0;
                g_scores[((size_t)h*kT+qi)*kT + c0+1] = v1;
            }
        }
}

__global__ void softmax_kernel(){
    const int q = blockIdx.x, h = blockIdx.y, tid = threadIdx.x;
    float4* row4 = (float4*)(g_scores + ((size_t)h*kT + q)*kT);
    const int n4 = ((q>>7)+1) << 5;
    __shared__ float sh[256];
    float lmax = -3.4e38f;
    for (int i = tid; i < n4; i += 256) {
        float4 v = row4[i];
        lmax = fmaxf(lmax, fmaxf(fmaxf(v.x, v.y), fmaxf(v.z, v.w)));
    }
    sh[tid] = lmax; __syncthreads();
    for (int s = 128; s > 0; s >>= 1) { if (tid < s) sh[tid] = fmaxf(sh[tid], sh[tid+s]); __syncthreads(); }
    float m = sh[0]; __syncthreads();
    float lsum = 0.f;
    for (int i = tid; i < n4; i += 256) {
        float4 v = row4[i];
        v.x = __expf(v.x - m); v.y = __expf(v.y - m);
        v.z = __expf(v.z - m); v.w = __expf(v.w - m);
        row4[i] = v;
        lsum += v.x + v.y + v.z + v.w;
    }
    sh[tid] = lsum; __syncthreads();
    for (int s = 128; s > 0; s >>= 1) { if (tid < s) sh[tid] += sh[tid+s]; __syncthreads(); }
    float inv = 1.f/sh[0];
    for (int i = tid; i < n4; i += 256) {
        float4 v = row4[i];
        row4[i] = make_float4(rtf(v.x*inv), rtf(v.y*inv), rtf(v.z*inv), rtf(v.w*inv));
    }
}

__global__ void __launch_bounds__(256,2) pv_kernel(){
    const int qt = blockIdx.x, h = blockIdx.y;
    extern __shared__ unsigned smw[];
    unsigned* As = smw;
    unsigned* Bs = smw + kStages*kABuf;
    const int row0 = qt*128;
    const int Kdim = (qt+1)*128;
    const float* A = g_scores + ((size_t)h*kT + row0)*kT;
    const float* B = g_qkv + (kNH+kNKV)*kHD + (h>>2)*kHD;
    const int tid = threadIdx.x, lane = tid&31, warp = tid>>5;
    const int wm = (warp&1)*64, wn = (warp>>1)*32;
    const int g = lane>>2, t = lane&3;
    const int nk = Kdim >> 5;
    auto issue = [&](int s){
        unsigned* Ad = As + (s%kStages)*kABuf;
        unsigned* Bd = Bs + (s%kStages)*kBBuf;
        int kk0 = s*32;
        #pragma unroll
        for (int q = 0; q < 4; q++) {
            int e = tid + q*256;
            int m = e>>3, k4 = e&7;
            cp16(sptr(Ad + m*kSA + k4*4), A + (size_t)m*kT + kk0 + k4*4);
        }
        #pragma unroll
        for (int q = 0; q < 4; q++) {
            int e = tid + q*256;
            int k = e>>5, n16 = e&31;
            cp16(sptr(Bd + k*kSB + n16*4), B + (size_t)(kk0+k)*kQKV + n16*4);
        }
        cp_commit();
    };
    for (int s = 0; s < kStages-1; s++) { if (s < nk) issue(s); else cp_commit(); }
    const unsigned aO = a_off(wm,lane);
    float acc[4][4][4] = {};
    for (int i = 0; i < nk; i++) {
        cp_wait1();
        __syncthreads();
        int s = i + kStages - 1;
        if (s < nk) issue(s); else cp_commit();
        int p = i % kStages;
        compute_plain<false>(sptr(As+p*kABuf)+aO, Bs+p*kBBuf, wn, g, t, acc);
    }
    #pragma unroll
    for (int im = 0; im < 4; im++)
        #pragma unroll
        for (int jn = 0; jn < 4; jn++) {
            int r0 = row0 + wm + im*16 + g;
            int c0 = wn + jn*8 + 2*t;
            #pragma unroll
            for (int hh = 0; hh < 2; hh++) {
                int rr = r0 + hh*8;
                g_attn[(size_t)rr*kH + h*kHD + c0]   = rtf(acc[im][jn][hh*2+0]);
                g_attn[(size_t)rr*kH + h*kHD + c0+1] = rtf(acc[im][jn][hh*2+1]);
            }
        }
}

__global__ void router_kernel(const float* __restrict__ gate_w){
    const int t = blockIdx.x, tid = threadIdx.x;
    const float* hp = g_h2f + (size_t)t*kH;
    float acc[kE] = {};
    for (int k = tid; k < kH; k += 256) {
        float hv = hp[k];
        const float* gw = gate_w + (size_t)k*kE;
        #pragma unroll
        for (int e = 0; e < kE; e++) acc[e] += hv*gw[e];
    }
    __shared__ float sh[kE][256];
    #pragma unroll
    for (int e = 0; e < kE; e++) sh[e][tid] = acc[e];
    __syncthreads();
    for (int s = 128; s > 0; s >>= 1) {
        if (tid < s) {
            #pragma unroll
            for (int e = 0; e < kE; e++) sh[e][tid] += sh[e][tid+s];
        }
        __syncthreads();
    }
    if (tid == 0) {
        float l[kE], mx = -3.4e38f;
        #pragma unroll
        for (int e = 0; e < kE; e++) { l[e] = sh[e][0]; mx = fmaxf(mx, l[e]); }
        float sum = 0.f;
        #pragma unroll
        for (int e = 0; e < kE; e++) { l[e] = __expf(l[e]-mx); sum += l[e]; }
        float isum = 1.f/sum;
        float best = -1.f, second = -1.f; int bi = 0, si = 0;
        #pragma unroll
        for (int e = 0; e < kE; e++) {
            float p = l[e]*isum;
            if (p > best) { second = best; si = bi; best = p; bi = e; }
            else if (p > second) { second = p; si = e; }
        }
        float denom = 1.f/(best + second);
        g_topi[t*2]   = bi; g_topw[t*2]   = best*denom;
        g_topi[t*2+1] = si; g_topw[t*2+1] = second*denom;
        atomicAdd(&g_cnt[bi], 1);
        atomicAdd(&g_cnt[si], 1);
    }
}

__global__ void moe_init_kernel(){
    int i = blockIdx.x*256 + threadIdx.x;
    if (i < kE) g_cnt[i] = 0;
    if (i < kSlots) g_tok[i] = kT;
    if (i < kH) g_h2[(size_t)kT*kH + i] = 0.f;
}
__global__ void moe_setup_kernel(){
    int off = 0, tile = 0;
    for (int e = 0; e < kE; e++) {
        g_cursor[e] = off;
        int seg = ((g_cnt[e] + 127)/128)*128;
        for (int i = 0; i < seg/128; i++) g_tile_e[tile++] = e;
        off += seg;
    }
    g_ntiles = tile;
}
__global__ void moe_scatter_kernel(){
    int t = blockIdx.x*256 + threadIdx.x;
    if (t >= kT) return;
    #pragma unroll
    for (int k = 0; k < 2; k++) {
        int e = g_topi[t*2+k];
        int pos = atomicAdd(&g_cursor[e], 1);
        g_tok[pos] = t;
        g_wt[pos]  = g_topw[t*2+k];
        g_slot_of[t*2+k] = pos;
    }
}

// ---------------- MoE gate_up: split-K2, partials into g_scores ----------------
__global__ void __launch_bounds__(256,2) moe_gu_kernel(const float* __restrict__ w_gate_up){
    const int tile = blockIdx.x;
    if (tile >= g_ntiles) return;
    extern __shared__ unsigned smw[];
    unsigned* As = smw;
    unsigned* Bs = smw + kStages*kABuf;
    __shared__ int rows[128];
    const int tid = threadIdx.x;
    if (tid < 128) rows[tid] = g_tok[tile*128 + tid];
    __syncthreads();
    const int e = g_tile_e[tile];
    const int col0 = blockIdx.y*128;
    const int koff = blockIdx.z*(kH/2);
    const float* Bb = w_gate_up + (size_t)e*kH*2*kI + (size_t)koff*(2*kI) + col0;
    float* P = g_scores + (size_t)blockIdx.z*kSlots*2*kI;
    const int lane = tid&31, warp = tid>>5;
    const int wm = (warp&1)*64, wn = (warp>>1)*32;
    const int g = lane>>2, t = lane&3;
    const int nk = (kH/2) >> 5;
    auto issue = [&](int s){
        unsigned* Ad = As + (s%kStages)*kABuf;
        unsigned* Bd = Bs + (s%kStages)*kBBuf;
        int kk0 = s*32;
        #pragma unroll
        for (int q = 0; q < 4; q++) {
            int ee = tid + q*256;
            int m = ee>>3, k4 = ee&7;
            cp16(sptr(Ad + m*kSA + k4*4), g_h2 + (size_t)rows[m]*kH + koff + kk0 + k4*4);
        }
        #pragma unroll
        for (int q = 0; q < 4; q++) {
            int ee = tid + q*256;
            int k = ee>>5, n16 = ee&31;
            cp16(sptr(Bd + k*kSB + n16*4), Bb + (size_t)(kk0+k)*(2*kI) + n16*4);
        }
        cp_commit();
    };
    for (int s = 0; s < kStages-1; s++) { if (s < nk) issue(s); else cp_commit(); }
    const unsigned aO = a_off(wm,lane);
    float acc[4][4][4] = {};
    for (int i = 0; i < nk; i++) {
        cp_wait1();
        __syncthreads();
        int s = i + kStages - 1;
        if (s < nk) issue(s); else cp_commit();
        int p = i % kStages;
        compute_plain<true>(sptr(As+p*kABuf)+aO, Bs+p*kBBuf, wn, g, t, acc);
    }
    #pragma unroll
    for (int im = 0; im < 4; im++)
        #pragma unroll
        for (int jn = 0; jn < 4; jn++) {
            int r0 = wm + im*16 + g;
            int c0 = col0 + wn + jn*8 + 2*t;
            #pragma unroll
            for (int hh = 0; hh < 2; hh++) {
                int slot = tile*128 + r0 + hh*8;
                P[(size_t)slot*2*kI + c0]   = acc[im][jn][hh*2+0];
                P[(size_t)slot*2*kI + c0+1] = acc[im][jn][hh*2+1];
            }
        }
}

// silu fuses gu split-K reduce: reads p0+p1 from g_scores
__global__ void silu_kernel(){
    int idx = blockIdx.x*256 + threadIdx.x;
    int slot = idx / (kI/4), j4 = idx % (kI/4);
    if (slot >= g_ntiles*128) return;
    const float4* p0 = (const float4*)(g_scores + (size_t)slot*2*kI);
    const float4* p1 = (const float4*)(g_scores + (size_t)kSlots*2*kI + (size_t)slot*2*kI);
    float4 g0 = p0[j4],        g1 = p1[j4];
    float4 u0 = p0[kI/4 + j4], u1 = p1[kI/4 + j4];
    float4 gv = make_float4(g0.x+g1.x, g0.y+g1.y, g0.z+g1.z, g0.w+g1.w);
    float4 uv = make_float4(u0.x+u1.x, u0.y+u1.y, u0.z+u1.z, u0.w+u1.w);
    float4 o;
    o.x = rtf((gv.x / (1.f + __expf(-gv.x))) * uv.x);
    o.y = rtf((gv.y / (1.f + __expf(-gv.y))) * uv.y);
    o.z = rtf((gv.z / (1.f + __expf(-gv.z))) * uv.z);
    o.w = rtf((gv.w / (1.f + __expf(-gv.w))) * uv.w);
    ((float4*)(g_act))[(size_t)slot*(kI/4) + j4] = o;
}

// ---------------- MoE down: split-K2, partials into g_scores ----------------
__global__ void __launch_bounds__(256,2) moe_down_kernel(const float* __restrict__ w_down){
    const int tile = blockIdx.x;
    if (tile >= g_ntiles) return;
    extern __shared__ unsigned smw[];
    unsigned* As = smw;
    unsigned* Bs = smw + kStages*kABuf;
    const int e = g_tile_e[tile];
    const int col0 = blockIdx.y*128;
    const int koff = blockIdx.z*(kI/2);
    const float* A  = g_act + (size_t)tile*128*kI + koff;
    const float* Bb = w_down + (size_t)e*kI*kH + (size_t)koff*kH + col0;
    float* P = g_scores + (size_t)blockIdx.z*kSlots*kH;
    const int tid = threadIdx.x, lane = tid&31, warp = tid>>5;
    const int wm = (warp&1)*64, wn = (warp>>1)*32;
    const int g = lane>>2, t = lane&3;
    const int nk = (kI/2) >> 5;
    auto issue = [&](int s){
        unsigned* Ad = As + (s%kStages)*kABuf;
        unsigned* Bd = Bs + (s%kStages)*kBBuf;
        int kk0 = s*32;
        #pragma unroll
        for (int q = 0; q < 4; q++) {
            int ee = tid + q*256;
            int m = ee>>3, k4 = ee&7;
            cp16(sptr(Ad + m*kSA + k4*4), A + (size_t)m*kI + kk0 + k4*4);
        }
        #pragma unroll
        for (int q = 0; q < 4; q++) {
            int ee = tid + q*256;
            int k = ee>>5, n16 = ee&31;
            cp16(sptr(Bd + k*kSB + n16*4), Bb + (size_t)(kk0+k)*kH + n16*4);
        }
        cp_commit();
    };
    for (int s = 0; s < kStages-1; s++) { if (s < nk) issue(s); else cp_commit(); }
    const unsigned aO = a_off(wm,lane);
    float acc[4][4][4] = {};
    for (int i = 0; i < nk; i++) {
        cp_wait1();
        __syncthreads();
        int s = i + kStages - 1;
        if (s < nk) issue(s); else cp_commit();
        int p = i % kStages;
        compute_plain<true>(sptr(As+p*kABuf)+aO, Bs+p*kBBuf, wn, g, t, acc);
    }
    #pragma unroll
    for (int im = 0; im < 4; im++)
        #pragma unroll
        for (int jn = 0; jn < 4; jn++) {
            int r0 = wm + im*16 + g;
            int c0 = col0 + wn + jn*8 + 2*t;
            #pragma unroll
            for (int hh = 0; hh < 2; hh++) {
                int slot = tile*128 + r0 + hh*8;
                P[(size_t)slot*kH + c0]   = acc[im][jn][hh*2+0];
                P[(size_t)slot*kH + c0+1] = acc[im][jn][hh*2+1];
            }
        }
}

// combine fuses down split-K reduce
__global__ void combine_kernel(float* __restrict__ out){
    const int t = blockIdx.x;
    const int s0 = g_slot_of[t*2], s1 = g_slot_of[t*2+1];
    const float w0 = g_wt[s0], w1 = g_wt[s1];
    const float4* a0 = (const float4*)(g_scores + (size_t)s0*kH);
    const float4* a1 = (const float4*)(g_scores + (size_t)kSlots*kH + (size_t)s0*kH);
    const float4* b0 = (const float4*)(g_scores + (size_t)s1*kH);
    const float4* b1 = (const float4*)(g_scores + (size_t)kSlots*kH + (size_t)s1*kH);
    float4* o = (float4*)(out + (size_t)t*kH);
    for (int j = threadIdx.x; j < kH/4; j += 256) {
        float4 x0 = a0[j], x1 = a1[j], y0 = b0[j], y1 = b1[j];
        o[j] = make_float4(w0*(x0.x+x1.x) + w1*(y0.x+y1.x),
                           w0*(x0.y+x1.y) + w1*(y0.y+y1.y),
                           w0*(x0.z+x1.z) + w1*(y0.z+y1.z),
                           w0*(x0.w+x1.w) + w1*(y0.w+y1.w));
    }
}

extern "C" void kernel_launch(void* const* d_in, const int* in_sizes, int n_in,
                              void* d_out, int out_size) {
    const int*   positions = (const int*)  d_in[0];
    const float* hidden    = (const float*)d_in[1];
    const float* residual  = (const float*)d_in[2];
    const float* w_qkv     = (const float*)d_in[3];
    const float* w_o       = (const float*)d_in[4];
    const float* q_norm_w  = (const float*)d_in[5];
    const float* k_norm_w  = (const float*)d_in[6];
    const float* ln1_w     = (const float*)d_in[7];
    const float* ln2_w     = (const float*)d_in[8];
    const float* gate_w    = (const float*)d_in[9];
    const float* w_gate_up = (const float*)d_in[10];
    const float* w_down    = (const float*)d_in[11];
    float* out = (float*)d_out;
    float* res = out + (size_t)kT*kH;

    float* d_h1;   cudaGetSymbolAddress((void**)&d_h1,  g_h1);
    float* d_part; cudaGetSymbolAddress((void**)&d_part,g_part);
    float* d_attn; cudaGetSymbolAddress((void**)&d_attn,g_attn);
    float* d_h2;   cudaGetSymbolAddress((void**)&d_h2,  g_h2);
    float* d_h2f;  cudaGetSymbolAddress((void**)&d_h2f, g_h2f);

    cudaFuncSetAttribute(gemm_splitk_kernel, cudaFuncAttributeMaxDynamicSharedMemorySize, (int)kPlainSmem);
    cudaFuncSetAttribute(scores_kernel,      cudaFuncAttributeMaxDynamicSharedMemorySize, (int)kTTSmem);
    cudaFuncSetAttribute(pv_kernel,          cudaFuncAttributeMaxDynamicSharedMemorySize, (int)kPlainSmem);
    cudaFuncSetAttribute(moe_gu_kernel,      cudaFuncAttributeMaxDynamicSharedMemorySize, (int)kPlainSmem);
    cudaFuncSetAttribute(moe_down_kernel,    cudaFuncAttributeMaxDynamicSharedMemorySize, (int)kPlainSmem);

    add_rms_kernel<<<kT, 256>>>(hidden, residual, ln1_w, res, d_h1, nullptr);
    gemm_splitk_kernel<<<dim3(kT/128, kQKV/128, 2), 256, kPlainSmem>>>(d_h1, kH, w_qkv, kQKV, d_part, kQKV, kH);
    rope_kernel<<<dim3(kT, kNH + 2*kNKV), 128>>>(positions, q_norm_w, k_norm_w);
    scores_kernel<<<dim3(kT/128, kT/128, kNH), 256, kTTSmem>>>();
    softmax_kernel<<<dim3(kT, kNH), 256>>>();
    pv_kernel<<<dim3(kT/128, kNH), 256, kPlainSmem>>>();
    gemm_splitk_kernel<<<dim3(kT/128, kH/128, 2), 256, kPlainSmem>>>(d_attn, kH, w_o, kH, d_part, kH, kH);
    add_rms3_kernel<<<kT, 256>>>(d_part, d_part + (size_t)kT*kH, ln2_w, res, d_h2, d_h2f);
    moe_init_kernel<<<(kSlots + 255)/256, 256>>>();
    router_kernel<<<kT, 256>>>(gate_w);
    moe_setup_kernel<<<1, 1>>>();
    moe_scatter_kernel<<<(kT + 255)/256, 256>>>();
    moe_gu_kernel<<<dim3(kTiles, 2*kI/128, 2), 256, kPlainSmem>>>(w_gate_up);
    silu_kernel<<<(kSlots*(kI/4) + 255)/256, 256>>>();
    moe_down_kernel<<<dim3(kTiles, kH/128, 2), 256, kPlainSmem>>>(w_down);
    combine_kernel<<<kT, 256>>>(out);
}

// round 17
// speedup vs baseline: 1.0920x; 1.0031x over previous
#include <cuda_runtime.h>
#include <math.h>

constexpr int kT=1024, kH=2048, kNH=16, kNKV=4, kHD=128, kE=8, kI=768;
constexpr int kQKV = kNH*kHD + 2*kNKV*kHD;
constexpr float kEPS=1e-6f, kScale=0.08838834764831845f;
constexpr int kSlots=3072, kTiles=kSlots/128, kStages=3;

__device__ float g_h1[kT*kH];
__device__ float g_qkv[kT*kQKV];
__device__ float g_part[2*kT*kQKV];
__device__ float g_scores[(size_t)kNH*kT*kT];   // also MoE split-K partial buffer
__device__ float g_rsum[kNH*kT];
__device__ float g_attn[kT*kH];
__device__ float g_h2[(kT+1)*kH];
__device__ float g_h2f[kT*kH];
__device__ float g_act[(size_t)kSlots*kI];
__device__ int   g_tok[kSlots];
__device__ float g_wt[kSlots];
__device__ int   g_slot_of[kT*2];
__device__ int   g_topi[kT*2];
__device__ float g_topw[kT*2];
__device__ int   g_cnt[kE];
__device__ int   g_cursor[kE];
__device__ int   g_tile_e[kTiles];
__device__ int   g_ntiles;

__device__ __forceinline__ unsigned f2tf(float x){unsigned r;asm("cvt.rna.tf32.f32 %0, %1;":"=r"(r):"f"(x));return r;}
__device__ __forceinline__ float rtf(float x){return __uint_as_float(f2tf(x));}
__device__ __forceinline__ void mma_tf32(float c[4],unsigned a0,unsigned a1,unsigned a2,unsigned a3,unsigned b0,unsigned b1){
    asm volatile("mma.sync.aligned.m16n8k8.row.col.f32.tf32.tf32.f32 {%0,%1,%2,%3}, {%4,%5,%6,%7}, {%8,%9}, {%0,%1,%2,%3};"
                 :"+f"(c[0]),"+f"(c[1]),"+f"(c[2]),"+f"(c[3]):"r"(a0),"r"(a1),"r"(a2),"r"(a3),"r"(b0),"r"(b1));
}
__device__ __forceinline__ unsigned sptr(const void* p){return (unsigned)__cvta_generic_to_shared(p);}
__device__ __forceinline__ void cp16(unsigned d,const void* s){asm volatile("cp.async.cg.shared.global [%0], [%1], 16;"::"r"(d),"l"(s));}
__device__ __forceinline__ void cp_commit(){asm volatile("cp.async.commit_group;");}
__device__ __forceinline__ void cp_wait1(){asm volatile("cp.async.wait_group 1;");}
__device__ __forceinline__ void ldsm4(unsigned&r0,unsigned&r1,unsigned&r2,unsigned&r3,unsigned a){
    asm volatile("ldmatrix.sync.aligned.m8n8.x4.shared.b16 {%0,%1,%2,%3}, [%4];":"=r"(r0),"=r"(r1),"=r"(r2),"=r"(r3):"r"(a));
}

constexpr int kSA=36, kSB=136, kABuf=128*kSA, kBBuf=32*kSB;
constexpr size_t kPlainSmem=(size_t)kStages*(kABuf+kBBuf)*4;
constexpr size_t kTTSmem=(size_t)kStages*2*kABuf*4;

__device__ __forceinline__ unsigned a_off(int wm,int lane){
    int sub=lane>>3, lr=lane&7;
    return 4u*((wm+(sub&1)*8+lr)*kSA + (sub>>1)*4);
}
__device__ __forceinline__ unsigned b_off(int wn,int p,int lane){
    int sub=lane>>3, lr=lane&7;
    return 4u*((wn+p*16+(sub>>1)*8+lr)*kSA + (sub&1)*4);
}
template <bool DoCvt>
__device__ __forceinline__ void compute_plain(unsigned aB,const unsigned* __restrict__ Bc,int wn,int g,int t,float acc[4][4][4]){
    #pragma unroll
    for (int kk = 0; kk < 32; kk += 8) {
        unsigned a[4][4], b[4][2];
        #pragma unroll
        for (int im = 0; im < 4; im++) ldsm4(a[im][0],a[im][1],a[im][2],a[im][3], aB+4u*(im*16*kSA+kk));
        #pragma unroll
        for (int jn = 0; jn < 4; jn++) {
            unsigned b0 = Bc[(kk+t)*kSB+wn+jn*8+g];
            unsigned b1 = Bc[(kk+t+4)*kSB+wn+jn*8+g];
            if (DoCvt) { b[jn][0]=f2tf(__uint_as_float(b0)); b[jn][1]=f2tf(__uint_as_float(b1)); }
            else       { b[jn][0]=b0; b[jn][1]=b1; }
        }
        #pragma unroll
        for (int im = 0; im < 4; im++)
            #pragma unroll
            for (int jn = 0; jn < 4; jn++)
                mma_tf32(acc[im][jn],a[im][0],a[im][1],a[im][2],a[im][3],b[jn][0],b[jn][1]);
    }
}
__device__ __forceinline__ void compute_tt(unsigned aB,unsigned b0a,unsigned b1a,float acc[4][4][4]){
    #pragma unroll
    for (int kk = 0; kk < 32; kk += 8) {
        unsigned a[4][4], b[4][2];
        #pragma unroll
        for (int im = 0; im < 4; im++) ldsm4(a[im][0],a[im][1],a[im][2],a[im][3], aB+4u*(im*16*kSA+kk));
        ldsm4(b[0][0],b[0][1],b[1][0],b[1][1], b0a+4u*kk);
        ldsm4(b[2][0],b[2][1],b[3][0],b[3][1], b1a+4u*kk);
        #pragma unroll
        for (int im = 0; im < 4; im++)
            #pragma unroll
            for (int jn = 0; jn < 4; jn++)
                mma_tf32(acc[im][jn],a[im][0],a[im][1],a[im][2],a[im][3],b[jn][0],b[jn][1]);
    }
}

__global__ void add_rms_kernel(const float* __restrict__ x,const float* __restrict__ r,
                               const float* __restrict__ w,float* __restrict__ res_out,
                               float* __restrict__ h_out,float* __restrict__ h_full){
    const int t = blockIdx.x, tid = threadIdx.x;
    const float4* xp = (const float4*)(x + (size_t)t*kH);
    const float4* rp = r ? (const float4*)(r + (size_t)t*kH) : nullptr;
    float4 v[2]; float ss = 0.f;
    #pragma unroll
    for (int i = 0; i < 2; i++) {
        int idx = tid + i*256;
        float4 a = xp[idx];
        if (rp) { float4 b = rp[idx]; a.x+=b.x; a.y+=b.y; a.z+=b.z; a.w+=b.w; }
        v[i] = a; ss += a.x*a.x + a.y*a.y + a.z*a.z + a.w*a.w;
    }
    __shared__ float sh[256];
    sh[tid] = ss; __syncthreads();
    for (int s = 128; s > 0; s >>= 1) { if (tid < s) sh[tid] += sh[tid+s]; __syncthreads(); }
    float scale = rsqrtf(sh[0]/(float)kH + kEPS);
    #pragma unroll
    for (int i = 0; i < 2; i++) {
        int idx = tid + i*256;
        if (res_out) ((float4*)(res_out + (size_t)t*kH))[idx] = v[i];
        float4 wv = ((const float4*)w)[idx];
        float4 hv = make_float4(v[i].x*scale*wv.x, v[i].y*scale*wv.y,
                                v[i].z*scale*wv.z, v[i].w*scale*wv.w);
        ((float4*)(h_out + (size_t)t*kH))[idx] =
            make_float4(rtf(hv.x), rtf(hv.y), rtf(hv.z), rtf(hv.w));
        if (h_full) ((float4*)(h_full + (size_t)t*kH))[idx] = hv;
    }
}

__global__ void add_rms3_kernel(const float* __restrict__ p0,const float* __restrict__ p1,
                                const float* __restrict__ w,float* __restrict__ res_io,
                                float* __restrict__ h_out,float* __restrict__ h_full){
    const int t = blockIdx.x, tid = threadIdx.x;
    float4 v[2]; float ss = 0.f;
    #pragma unroll
    for (int i = 0; i < 2; i++) {
        int idx = tid + i*256;
        size_t o = (size_t)t*(kH/4) + idx;
        float4 a = ((const float4*)p0)[o];
        float4 b = ((const float4*)p1)[o];
        float4 c = ((const float4*)res_io)[o];
        float4 s4 = make_float4(a.x+b.x+c.x, a.y+b.y+c.y, a.z+b.z+c.z, a.w+b.w+c.w);
        v[i] = s4; ss += s4.x*s4.x + s4.y*s4.y + s4.z*s4.z + s4.w*s4.w;
    }
    __shared__ float sh[256];
    sh[tid] = ss; __syncthreads();
    for (int s = 128; s > 0; s >>= 1) { if (tid < s) sh[tid] += sh[tid+s]; __syncthreads(); }
    float scale = rsqrtf(sh[0]/(float)kH + kEPS);
    #pragma unroll
    for (int i = 0; i < 2; i++) {
        int idx = tid + i*256;
        size_t o = (size_t)t*(kH/4) + idx;
        ((float4*)res_io)[o] = v[i];
        float4 wv = ((const float4*)w)[idx];
        float4 hv = make_float4(v[i].x*scale*wv.x, v[i].y*scale*wv.y,
                                v[i].z*scale*wv.z, v[i].w*scale*wv.w);
        ((float4*)h_out)[o] = make_float4(rtf(hv.x), rtf(hv.y), rtf(hv.z), rtf(hv.w));
        if (h_full) ((float4*)h_full)[o] = hv;
    }
}

// ---------------- 128x128 GEMM; split factor = gridDim.z ----------------
__global__ void __launch_bounds__(256, 2)
gemm_splitk_kernel(const float* __restrict__ A,int lda,const float* __restrict__ B,int ldb,
                   float* __restrict__ Cpart,int ldc,int Kdim){
    extern __shared__ unsigned smem[];
    unsigned* As = smem;
    unsigned* Bs = smem + kStages*kABuf;
    const int row0 = blockIdx.x*128, col0 = blockIdx.y*128;
    const int Kpart = Kdim / gridDim.z;
    const int koff = blockIdx.z*Kpart;
    const int tid = threadIdx.x, lane = tid&31, warp = tid>>5;
    const int wm = (warp&1)*64, wn = (warp>>1)*32;
    const int g = lane>>2, t = lane&3;
    const float* Ab = A + (size_t)row0*lda + koff;
    const float* Bb = B + (size_t)koff*ldb + col0;
    float* C = Cpart + (size_t)blockIdx.z*kT*ldc;
    const int nk = Kpart >> 5;

    auto issue = [&](int s){
        unsigned* Ad = As + (s%kStages)*kABuf;
        unsigned* Bd = Bs + (s%kStages)*kBBuf;
        int kk0 = s*32;
        #pragma unroll
        for (int q = 0; q < 4; q++) {
            int e = tid + q*256;
            int m = e>>3, k4 = e&7;
            cp16(sptr(Ad + m*kSA + k4*4), Ab + (size_t)m*lda + kk0 + k4*4);
        }
        #pragma unroll
        for (int q = 0; q < 4; q++) {
            int e = tid + q*256;
            int k = e>>5, n16 = e&31;
            cp16(sptr(Bd + k*kSB + n16*4), Bb + (size_t)(kk0+k)*ldb + n16*4);
        }
        cp_commit();
    };
    for (int s = 0; s < kStages-1; s++) { if (s < nk) issue(s); else cp_commit(); }

    const unsigned aO = a_off(wm,lane);
    float acc[4][4][4] = {};
    for (int i = 0; i < nk; i++) {
        cp_wait1();
        __syncthreads();
        int s = i + kStages - 1;
        if (s < nk) issue(s); else cp_commit();
        compute_plain<true>(sptr(As + (i%kStages)*kABuf) + aO, Bs + (i%kStages)*kBBuf, wn, g, t, acc);
    }
    #pragma unroll
    for (int im = 0; im < 4; im++)
        #pragma unroll
        for (int jn = 0; jn < 4; jn++) {
            int r0 = row0 + wm + im*16 + g;
            int c0 = col0 + wn + jn*8 + 2*t;
            #pragma unroll
            for (int hh = 0; hh < 2; hh++) {
                int rr = r0 + hh*8;
                C[(size_t)rr*ldc + c0]   = acc[im][jn][hh*2+0];
                C[(size_t)rr*ldc + c0+1] = acc[im][jn][hh*2+1];
            }
        }
}

// ---------------- QK-RMSNorm + RoPE; fuses QKV split-K reduce ----------------
__global__ void rope_kernel(const int* __restrict__ positions,const float* __restrict__ q_norm_w,
                            const float* __restrict__ k_norm_w){
    const int t = blockIdx.x, hh = blockIdx.y, lane = threadIdx.x;
    const float* p0 = g_part;
    const float* p1 = g_part + (size_t)kT*kQKV;
    if (hh >= kNH + kNKV) {
        int vh = hh - kNH - kNKV;
        size_t o = (size_t)t*kQKV + (kNH+kNKV)*kHD + vh*kHD + lane;
        g_qkv[o] = rtf(p0[o] + p1[o]);
        return;
    }
    const size_t base = (size_t)t*kQKV + (hh < kNH ? hh*kHD : kNH*kHD + (hh-kNH)*kHD);
    const float* nw = (hh < kNH) ? q_norm_w : k_norm_w;
    float v = p0[base + lane] + p1[base + lane];
    __shared__ float sred[128];
    sred[lane] = v*v; __syncthreads();
    for (int s = 64; s > 0; s >>= 1) { if (lane < s) sred[lane] += sred[lane+s]; __syncthreads(); }
    float scale = rsqrtf(sred[0]/(float)kHD + kEPS);
    float xn = v*scale*nw[lane];
    __shared__ float sh[128];
    sh[lane] = xn; __syncthreads();
    int j = lane & 63;
    const float kLog2Theta_64 = 19.931568569324174f / 64.0f;
    float inv = exp2f(-(float)j * kLog2Theta_64);
    float ang = (float)positions[t] * inv;
    float s, c;
    sincosf(ang, &s, &c);
    float outv = (lane < 64) ? sh[lane]*c - sh[lane+64]*s : sh[lane]*c + sh[lane-64]*s;
    g_qkv[base + lane] = rtf(outv);
}

__global__ void __launch_bounds__(256,2) scores_kernel(){
    const int qt = blockIdx.x, kt = blockIdx.y, h = blockIdx.z;
    if (kt > qt) return;
    extern __shared__ unsigned smw[];
    unsigned* As = smw;
    unsigned* Bst = smw + kStages*kABuf;
    const float* Q  = g_qkv + (size_t)qt*128*kQKV + h*kHD;
    const float* Kp = g_qkv + (size_t)kt*128*kQKV + kNH*kHD + (h>>2)*kHD;
    const int tid = threadIdx.x, lane = tid&31, warp = tid>>5;
    const int wm = (warp&1)*64, wn = (warp>>1)*32;
    const int g = lane>>2, t = lane&3;
    const int nk = kHD >> 5;
    auto issue = [&](int s){
        unsigned* Ad = As + (s%kStages)*kABuf;
        unsigned* Bd = Bst + (s%kStages)*kABuf;
        int kk0 = s*32;
        #pragma unroll
        for (int q = 0; q < 4; q++) {
            int e = tid + q*256;
            int m = e>>3, k4 = e&7;
            cp16(sptr(Ad + m*kSA + k4*4), Q  + (size_t)m*kQKV + kk0 + k4*4);
            cp16(sptr(Bd + m*kSA + k4*4), Kp + (size_t)m*kQKV + kk0 + k4*4);
        }
        cp_commit();
    };
    for (int s = 0; s < kStages-1; s++) { if (s < nk) issue(s); else cp_commit(); }
    const unsigned aO = a_off(wm,lane), b0 = b_off(wn,0,lane), b1 = b_off(wn,1,lane);
    float acc[4][4][4] = {};
    for (int i = 0; i < nk; i++) {
        cp_wait1();
        __syncthreads();
        int s = i + kStages - 1;
        if (s < nk) issue(s); else cp_commit();
        int p = i % kStages;
        compute_tt(sptr(As+p*kABuf)+aO, sptr(Bst+p*kABuf)+b0, sptr(Bst+p*kABuf)+b1, acc);
    }
    const int row0 = qt*128, col0 = kt*128;
    #pragma unroll
    for (int im = 0; im < 4; im++)
        #pragma unroll
        for (int jn = 0; jn < 4; jn++) {
            int r0 = row0 + wm + im*16 + g;
            int c0 = col0 + wn + jn*8 + 2*t;
            #pragma unroll
            for (int hh = 0; hh < 2; hh++) {
                int qi = r0 + hh*8;
                float v0 = acc[im][jn][hh*2+0]*kScale;
                float v1 = acc[im][jn][hh*2+1]*kScale;
                if (c0   > qi) v0 = -1e9f;
                if (c0+1 > qi) v1 = -1e9f;
                g_scores[((size_t)h*kT+qi)*kT + c0]   = v0;
                g_scores[((size_t)h*kT+qi)*kT + c0+1] = v1;
            }
        }
}

// ---------------- softmax: 2 passes; writes rtf(exp(s-m)) unnormalized, stores row sum ----------------
__global__ void softmax_kernel(){
    const int q = blockIdx.x, h = blockIdx.y, tid = threadIdx.x;
    float4* row4 = (float4*)(g_scores + ((size_t)h*kT + q)*kT);
    const int n4 = ((q>>7)+1) << 5;
    __shared__ float sh[256];
    float lmax = -3.4e38f;
    for (int i = tid; i < n4; i += 256) {
        float4 v = row4[i];
        lmax = fmaxf(lmax, fmaxf(fmaxf(v.x, v.y), fmaxf(v.z, v.w)));
    }
    sh[tid] = lmax; __syncthreads();
    for (int s = 128; s > 0; s >>= 1) { if (tid < s) sh[tid] = fmaxf(sh[tid], sh[tid+s]); __syncthreads(); }
    float m = sh[0]; __syncthreads();
    float lsum = 0.f;
    for (int i = tid; i < n4; i += 256) {
        float4 v = row4[i];
        v.x = __expf(v.x - m); v.y = __expf(v.y - m);
        v.z = __expf(v.z - m); v.w = __expf(v.w - m);
        lsum += v.x + v.y + v.z + v.w;
        row4[i] = make_float4(rtf(v.x), rtf(v.y), rtf(v.z), rtf(v.w));
    }
    sh[tid] = lsum; __syncthreads();
    for (int s = 128; s > 0; s >>= 1) { if (tid < s) sh[tid] += sh[tid+s]; __syncthreads(); }
    if (tid == 0) g_rsum[h*kT + q] = sh[0];
}

// ---------------- PV: split-K2, unnormalized P; partials into g_part ----------------
__global__ void __launch_bounds__(256,2) pv_kernel(){
    const int qt = blockIdx.x, h = blockIdx.y;
    extern __shared__ unsigned smw[];
    unsigned* As = smw;
    unsigned* Bs = smw + kStages*kABuf;
    const int row0 = qt*128;
    const int Kpart = (qt+1)*64;              // half of (qt+1)*128, multiple of 32... (qt+1)*64 >= 64
    const int koff = blockIdx.z*Kpart;
    const float* A = g_scores + ((size_t)h*kT + row0)*kT + koff;
    const float* B = g_qkv + (kNH+kNKV)*kHD + (h>>2)*kHD + (size_t)koff*kQKV;
    float* P = g_part + (size_t)blockIdx.z*kT*kH;
    const int tid = threadIdx.x, lane = tid&31, warp = tid>>5;
    const int wm = (warp&1)*64, wn = (warp>>1)*32;
    const int g = lane>>2, t = lane&3;
    const int nk = Kpart >> 5;
    auto issue = [&](int s){
        unsigned* Ad = As + (s%kStages)*kABuf;
        unsigned* Bd = Bs + (s%kStages)*kBBuf;
        int kk0 = s*32;
        #pragma unroll
        for (int q = 0; q < 4; q++) {
            int e = tid + q*256;
            int m = e>>3, k4 = e&7;
            cp16(sptr(Ad + m*kSA + k4*4), A + (size_t)m*kT + kk0 + k4*4);
        }
        #pragma unroll
        for (int q = 0; q < 4; q++) {
            int e = tid + q*256;
            int k = e>>5, n16 = e&31;
            cp16(sptr(Bd + k*kSB + n16*4), B + (size_t)(kk0+k)*kQKV + n16*4);
        }
        cp_commit();
    };
    for (int s = 0; s < kStages-1; s++) { if (s < nk) issue(s); else cp_commit(); }
    const unsigned aO = a_off(wm,lane);
    float acc[4][4][4] = {};
    for (int i = 0; i < nk; i++) {
        cp_wait1();
        __syncthreads();
        int s = i + kStages - 1;
        if (s < nk) issue(s); else cp_commit();
        int p = i % kStages;
        compute_plain<false>(sptr(As+p*kABuf)+aO, Bs+p*kBBuf, wn, g, t, acc);
    }
    #pragma unroll
    for (int im = 0; im < 4; im++)
        #pragma unroll
        for (int jn = 0; jn < 4; jn++) {
            int r0 = row0 + wm + im*16 + g;
            int c0 = wn + jn*8 + 2*t;
            #pragma unroll
            for (int hh = 0; hh < 2; hh++) {
                int rr = r0 + hh*8;
                P[(size_t)rr*kH + h*kHD + c0]   = acc[im][jn][hh*2+0];
                P[(size_t)rr*kH + h*kHD + c0+1] = acc[im][jn][hh*2+1];
            }
        }
}

// pv reduce: g_attn = rtf((p0+p1) * 1/rsum)
__global__ void pv_reduce_kernel(){
    const int t = blockIdx.x;
    const float4* p0 = (const float4*)(g_part + (size_t)t*kH);
    const float4* p1 = (const float4*)(g_part + (size_t)kT*kH + (size_t)t*kH);
    float4* o = (float4*)(g_attn + (size_t)t*kH);
    for (int j = threadIdx.x; j < kH/4; j += 256) {
        int h = (j*4)/kHD;
        float inv = 1.f/g_rsum[h*kT + t];
        float4 a = p0[j], b = p1[j];
        o[j] = make_float4(rtf((a.x+b.x)*inv), rtf((a.y+b.y)*inv),
                           rtf((a.z+b.z)*inv), rtf((a.w+b.w)*inv));
    }
}

__global__ void router_kernel(const float* __restrict__ gate_w){
    const int t = blockIdx.x, tid = threadIdx.x;
    const float* hp = g_h2f + (size_t)t*kH;
    float acc[kE] = {};
    for (int k = tid; k < kH; k += 256) {
        float hv = hp[k];
        const float* gw = gate_w + (size_t)k*kE;
        #pragma unroll
        for (int e = 0; e < kE; e++) acc[e] += hv*gw[e];
    }
    __shared__ float sh[kE][256];
    #pragma unroll
    for (int e = 0; e < kE; e++) sh[e][tid] = acc[e];
    __syncthreads();
    for (int s = 128; s > 0; s >>= 1) {
        if (tid < s) {
            #pragma unroll
            for (int e = 0; e < kE; e++) sh[e][tid] += sh[e][tid+s];
        }
        __syncthreads();
    }
    if (tid == 0) {
        float l[kE], mx = -3.4e38f;
        #pragma unroll
        for (int e = 0; e < kE; e++) { l[e] = sh[e][0]; mx = fmaxf(mx, l[e]); }
        float sum = 0.f;
        #pragma unroll
        for (int e = 0; e < kE; e++) { l[e] = __expf(l[e]-mx); sum += l[e]; }
        float isum = 1.f/sum;
        float best = -1.f, second = -1.f; int bi = 0, si = 0;
        #pragma unroll
        for (int e = 0; e < kE; e++) {
            float p = l[e]*isum;
            if (p > best) { second = best; si = bi; best = p; bi = e; }
            else if (p > second) { second = p; si = e; }
        }
        float denom = 1.f/(best + second);
        g_topi[t*2]   = bi; g_topw[t*2]   = best*denom;
        g_topi[t*2+1] = si; g_topw[t*2+1] = second*denom;
        atomicAdd(&g_cnt[bi], 1);
        atomicAdd(&g_cnt[si], 1);
    }
}

__global__ void moe_init_kernel(){
    int i = blockIdx.x*256 + threadIdx.x;
    if (i < kE) g_cnt[i] = 0;
    if (i < kSlots) g_tok[i] = kT;
    if (i < kH) g_h2[(size_t)kT*kH + i] = 0.f;
}
__global__ void moe_setup_kernel(){
    int off = 0, tile = 0;
    for (int e = 0; e < kE; e++) {
        g_cursor[e] = off;
        int seg = ((g_cnt[e] + 127)/128)*128;
        for (int i = 0; i < seg/128; i++) g_tile_e[tile++] = e;
        off += seg;
    }
    g_ntiles = tile;
}
__global__ void moe_scatter_kernel(){
    int t = blockIdx.x*256 + threadIdx.x;
    if (t >= kT) return;
    #pragma unroll
    for (int k = 0; k < 2; k++) {
        int e = g_topi[t*2+k];
        int pos = atomicAdd(&g_cursor[e], 1);
        g_tok[pos] = t;
        g_wt[pos]  = g_topw[t*2+k];
        g_slot_of[t*2+k] = pos;
    }
}

__global__ void __launch_bounds__(256,2) moe_gu_kernel(const float* __restrict__ w_gate_up){
    const int tile = blockIdx.x;
    if (tile >= g_ntiles) return;
    extern __shared__ unsigned smw[];
    unsigned* As = smw;
    unsigned* Bs = smw + kStages*kABuf;
    __shared__ int rows[128];
    const int tid = threadIdx.x;
    if (tid < 128) rows[tid] = g_tok[tile*128 + tid];
    __syncthreads();
    const int e = g_tile_e[tile];
    const int col0 = blockIdx.y*128;
    const int koff = blockIdx.z*(kH/2);
    const float* Bb = w_gate_up + (size_t)e*kH*2*kI + (size_t)koff*(2*kI) + col0;
    float* P = g_scores + (size_t)blockIdx.z*kSlots*2*kI;
    const int lane = tid&31, warp = tid>>5;
    const int wm = (warp&1)*64, wn = (warp>>1)*32;
    const int g = lane>>2, t = lane&3;
    const int nk = (kH/2) >> 5;
    auto issue = [&](int s){
        unsigned* Ad = As + (s%kStages)*kABuf;
        unsigned* Bd = Bs + (s%kStages)*kBBuf;
        int kk0 = s*32;
        #pragma unroll
        for (int q = 0; q < 4; q++) {
            int ee = tid + q*256;
            int m = ee>>3, k4 = ee&7;
            cp16(sptr(Ad + m*kSA + k4*4), g_h2 + (size_t)rows[m]*kH + koff + kk0 + k4*4);
        }
        #pragma unroll
        for (int q = 0; q < 4; q++) {
            int ee = tid + q*256;
            int k = ee>>5, n16 = ee&31;
            cp16(sptr(Bd + k*kSB + n16*4), Bb + (size_t)(kk0+k)*(2*kI) + n16*4);
        }
        cp_commit();
    };
    for (int s = 0; s < kStages-1; s++) { if (s < nk) issue(s); else cp_commit(); }
    const unsigned aO = a_off(wm,lane);
    float acc[4][4][4] = {};
    for (int i = 0; i < nk; i++) {
        cp_wait1();
        __syncthreads();
        int s = i + kStages - 1;
        if (s < nk) issue(s); else cp_commit();
        int p = i % kStages;
        compute_plain<true>(sptr(As+p*kABuf)+aO, Bs+p*kBBuf, wn, g, t, acc);
    }
    #pragma unroll
    for (int im = 0; im < 4; im++)
        #pragma unroll
        for (int jn = 0; jn < 4; jn++) {
            int r0 = wm + im*16 + g;
            int c0 = col0 + wn + jn*8 + 2*t;
            #pragma unroll
            for (int hh = 0; hh < 2; hh++) {
                int slot = tile*128 + r0 + hh*8;
                P[(size_t)slot*2*kI + c0]   = acc[im][jn][hh*2+0];
                P[(size_t)slot*2*kI + c0+1] = acc[im][jn][hh*2+1];
            }
        }
}

__global__ void silu_kernel(){
    int idx = blockIdx.x*256 + threadIdx.x;
    int slot = idx / (kI/4), j4 = idx % (kI/4);
    if (slot >= g_ntiles*128) return;
    const float4* p0 = (const float4*)(g_scores + (size_t)slot*2*kI);
    const float4* p1 = (const float4*)(g_scores + (size_t)kSlots*2*kI + (size_t)slot*2*kI);
    float4 g0 = p0[j4],        g1 = p1[j4];
    float4 u0 = p0[kI/4 + j4], u1 = p1[kI/4 + j4];
    float4 gv = make_float4(g0.x+g1.x, g0.y+g1.y, g0.z+g1.z, g0.w+g1.w);
    float4 uv = make_float4(u0.x+u1.x, u0.y+u1.y, u0.z+u1.z, u0.w+u1.w);
    float4 o;
    o.x = rtf((gv.x / (1.f + __expf(-gv.x))) * uv.x);
    o.y = rtf((gv.y / (1.f + __expf(-gv.y))) * uv.y);
    o.z = rtf((gv.z / (1.f + __expf(-gv.z))) * uv.z);
    o.w = rtf((gv.w / (1.f + __expf(-gv.w))) * uv.w);
    ((float4*)(g_act))[(size_t)slot*(kI/4) + j4] = o;
}

__global__ void __launch_bounds__(256,2) moe_down_kernel(const float* __restrict__ w_down){
    const int tile = blockIdx.x;
    if (tile >= g_ntiles) return;
    extern __shared__ unsigned smw[];
    unsigned* As = smw;
    unsigned* Bs = smw + kStages*kABuf;
    const int e = g_tile_e[tile];
    const int col0 = blockIdx.y*128;
    const int koff = blockIdx.z*(kI/2);
    const float* A  = g_act + (size_t)tile*128*kI + koff;
    const float* Bb = w_down + (size_t)e*kI*kH + (size_t)koff*kH + col0;
    float* P = g_scores + (size_t)blockIdx.z*kSlots*kH;
    const int tid = threadIdx.x, lane = tid&31, warp = tid>>5;
    const int wm = (warp&1)*64, wn = (warp>>1)*32;
    const int g = lane>>2, t = lane&3;
    const int nk = (kI/2) >> 5;
    auto issue = [&](int s){
        unsigned* Ad = As + (s%kStages)*kABuf;
        unsigned* Bd = Bs + (s%kStages)*kBBuf;
        int kk0 = s*32;
        #pragma unroll
        for (int q = 0; q < 4; q++) {
            int ee = tid + q*256;
            int m = ee>>3, k4 = ee&7;
            cp16(sptr(Ad + m*kSA + k4*4), A + (size_t)m*kI + kk0 + k4*4);
        }
        #pragma unroll
        for (int q = 0; q < 4; q++) {
            int ee = tid + q*256;
            int k = ee>>5, n16 = ee&31;
            cp16(sptr(Bd + k*kSB + n16*4), Bb + (size_t)(kk0+k)*kH + n16*4);
        }
        cp_commit();
    };
    for (int s = 0; s < kStages-1; s++) { if (s < nk) issue(s); else cp_commit(); }
    const unsigned aO = a_off(wm,lane);
    float acc[4][4][4] = {};
    for (int i = 0; i < nk; i++) {
        cp_wait1();
        __syncthreads();
        int s = i + kStages - 1;
        if (s < nk) issue(s); else cp_commit();
        int p = i % kStages;
        compute_plain<true>(sptr(As+p*kABuf)+aO, Bs+p*kBBuf, wn, g, t, acc);
    }
    #pragma unroll
    for (int im = 0; im < 4; im++)
        #pragma unroll
        for (int jn = 0; jn < 4; jn++) {
            int r0 = wm + im*16 + g;
            int c0 = col0 + wn + jn*8 + 2*t;
            #pragma unroll
            for (int hh = 0; hh < 2; hh++) {
                int slot = tile*128 + r0 + hh*8;
                P[(size_t)slot*kH + c0]   = acc[im][jn][hh*2+0];
                P[(size_t)slot*kH + c0+1] = acc[im][jn][hh*2+1];
            }
        }
}

__global__ void combine_kernel(float* __restrict__ out){
    const int t = blockIdx.x;
    const int s0 = g_slot_of[t*2], s1 = g_slot_of[t*2+1];
    const float w0 = g_wt[s0], w1 = g_wt[s1];
    const float4* a0 = (const float4*)(g_scores + (size_t)s0*kH);
    const float4* a1 = (const float4*)(g_scores + (size_t)kSlots*kH + (size_t)s0*kH);
    const float4* b0 = (const float4*)(g_scores + (size_t)s1*kH);
    const float4* b1 = (const float4*)(g_scores + (size_t)kSlots*kH + (size_t)s1*kH);
    float4* o = (float4*)(out + (size_t)t*kH);
    for (int j = threadIdx.x; j < kH/4; j += 256) {
        float4 x0 = a0[j], x1 = a1[j], y0 = b0[j], y1 = b1[j];
        o[j] = make_float4(w0*(x0.x+x1.x) + w1*(y0.x+y1.x),
                           w0*(x0.y+x1.y) + w1*(y0.y+y1.y),
                           w0*(x0.z+x1.z) + w1*(y0.z+y1.z),
                           w0*(x0.w+x1.w) + w1*(y0.w+y1.w));
    }
}

extern "C" void kernel_launch(void* const* d_in, const int* in_sizes, int n_in,
                              void* d_out, int out_size) {
    const int*   positions = (const int*)  d_in[0];
    const float* hidden    = (const float*)d_in[1];
    const float* residual  = (const float*)d_in[2];
    const float* w_qkv     = (const float*)d_in[3];
    const float* w_o       = (const float*)d_in[4];
    const float* q_norm_w  = (const float*)d_in[5];
    const float* k_norm_w  = (const float*)d_in[6];
    const float* ln1_w     = (const float*)d_in[7];
    const float* ln2_w     = (const float*)d_in[8];
    const float* gate_w    = (const float*)d_in[9];
    const float* w_gate_up = (const float*)d_in[10];
    const float* w_down    = (const float*)d_in[11];
    float* out = (float*)d_out;
    float* res = out + (size_t)kT*kH;

    float* d_h1;   cudaGetSymbolAddress((void**)&d_h1,  g_h1);
    float* d_part; cudaGetSymbolAddress((void**)&d_part,g_part);
    float* d_attn; cudaGetSymbolAddress((void**)&d_attn,g_attn);
    float* d_h2;   cudaGetSymbolAddress((void**)&d_h2,  g_h2);
    float* d_h2f;  cudaGetSymbolAddress((void**)&d_h2f, g_h2f);

    cudaFuncSetAttribute(gemm_splitk_kernel, cudaFuncAttributeMaxDynamicSharedMemorySize, (int)kPlainSmem);
    cudaFuncSetAttribute(scores_kernel,      cudaFuncAttributeMaxDynamicSharedMemorySize, (int)kTTSmem);
    cudaFuncSetAttribute(pv_kernel,          cudaFuncAttributeMaxDynamicSharedMemorySize, (int)kPlainSmem);
    cudaFuncSetAttribute(moe_gu_kernel,      cudaFuncAttributeMaxDynamicSharedMemorySize, (int)kPlainSmem);
    cudaFuncSetAttribute(moe_down_kernel,    cudaFuncAttributeMaxDynamicSharedMemorySize, (int)kPlainSmem);

    add_rms_kernel<<<kT, 256>>>(hidden, residual, ln1_w, res, d_h1, nullptr);
    gemm_splitk_kernel<<<dim3(kT/128, kQKV/128, 2), 256, kPlainSmem>>>(d_h1, kH, w_qkv, kQKV, d_part, kQKV, kH);
    rope_kernel<<<dim3(kT, kNH + 2*kNKV), 128>>>(positions, q_norm_w, k_norm_w);
    scores_kernel<<<dim3(kT/128, kT/128, kNH), 256, kTTSmem>>>();
    softmax_kernel<<<dim3(kT, kNH), 256>>>();
    pv_kernel<<<dim3(kT/128, kNH, 2), 256, kPlainSmem>>>();
    pv_reduce_kernel<<<kT, 256>>>();
    gemm_splitk_kernel<<<dim3(kT/128, kH/128, 2), 256, kPlainSmem>>>(d_attn, kH, w_o, kH, d_part, kH, kH);
    add_rms3_kernel<<<kT, 256>>>(d_part, d_part + (size_t)kT*kH, ln2_w, res, d_h2, d_h2f);
    moe_init_kernel<<<(kSlots + 255)/256, 256>>>();
    router_kernel<<<kT, 256>>>(gate_w);
    moe_setup_kernel<<<1, 1>>>();
    moe_scatter_kernel<<<(kT + 255)/256, 256>>>();
    moe_gu_kernel<<<dim3(kTiles, 2*kI/128, 2), 256, kPlainSmem>>>(w_gate_up);
    silu_kernel<<<(kSlots*(kI/4) + 255)/256, 256>>>();
    moe_down_kernel<<<dim3(kTiles, kH/128, 2), 256, kPlainSmem>>>(w_down);
    combine_kernel<<<kT, 256>>>(out);
}